// round 14
// baseline (speedup 1.0000x reference)
#include <cuda_runtime.h>
#include <cuda_bf16.h>
#include <math.h>
#include <stdint.h>

// ---------------- problem constants ----------------
#define BB    2
#define NN    2048
#define CCH   512
#define KVL   2560          // CCH + NN
#define DM    768
#define NH    12
#define HD    64
#define FF    3072
#define KSZ   31
#define RR    (BB*NN)       // 4096 token rows
#define EPS   1e-5f

// ---------------- scratch (static device memory; no allocs) ----------------
__device__ float g_x   [RR*DM];
__device__ float g_ff  [RR*FF];          // fp32 GEMM outputs (pw1)
__device__ float g_qkv [RR*3*NH*HD];
__device__ float g_glu [RR*DM];
__device__ float g_dw  [RR*DM];
__device__ float g_mean[DM];
__device__ float g_var [DM];
__device__ float g_rs  [KVL*32];         // rope sin table
__device__ float g_rc  [KVL*32];         // rope cos table
#define BN_BLKS 128
__device__ float g_bnp1[BN_BLKS*DM];     // bn partial sums
__device__ float g_bnp2[BN_BLKS*DM];     // bn partial sumsq

#define WT_TOTAL 13565952
__device__ __align__(256) __nv_bfloat16 g_wth[WT_TOTAL];   // transposed weights hi
__device__ __align__(256) __nv_bfloat16 g_wtl[WT_TOTAL];   // transposed weights lo
__device__ __align__(256) __nv_bfloat16 g_abh[RR*FF];      // FF-wide activation hi
__device__ __align__(256) __nv_bfloat16 g_abl[RR*FF];      // FF-wide activation lo
__device__ __align__(256) __nv_bfloat16 g_a1h[RR*DM];      // DM-wide activation hi
__device__ __align__(256) __nv_bfloat16 g_a1l[RR*DM];      // DM-wide activation lo
__device__ __align__(256) __nv_bfloat16 g_qsh[RR*DM];      // Q split hi  [b,h,n,d] (scaled)
__device__ __align__(256) __nv_bfloat16 g_qsl[RR*DM];
#define KVE (BB*NH*KVL*HD)
__device__ __align__(256) __nv_bfloat16 g_ksh[KVE];        // roped K hi [b,h,p,d]
__device__ __align__(256) __nv_bfloat16 g_ksl[KVE];
__device__ __align__(256) __nv_bfloat16 g_vsh[KVE];        // V hi [b,h,p,d]
__device__ __align__(256) __nv_bfloat16 g_vsl[KVE];

// ================= PTX helpers (base sm_103-safe) ====
__device__ __forceinline__ uint32_t _s2u(const void* p){
    uint32_t a; asm("{ .reg .u64 t; cvta.to.shared.u64 t, %1; cvt.u32.u64 %0, t; }":"=r"(a):"l"(p)); return a;
}
#define CP16(d,s)   asm volatile("cp.async.cg.shared.global [%0], [%1], 16;"::"r"(d),"l"(s):"memory")
#define CPCOMMIT()  asm volatile("cp.async.commit_group;":::"memory")
#define CPWAITG(n)  asm volatile("cp.async.wait_group %0;"::"n"(n):"memory")

__device__ __forceinline__ void ldsm_x4(uint32_t a, uint32_t r[4]){
    asm volatile("ldmatrix.sync.aligned.m8n8.x4.shared.b16 {%0,%1,%2,%3}, [%4];"
        : "=r"(r[0]),"=r"(r[1]),"=r"(r[2]),"=r"(r[3]) : "r"(a));
}
__device__ __forceinline__ void ldsm_x2(uint32_t a, uint32_t r[2]){
    asm volatile("ldmatrix.sync.aligned.m8n8.x2.shared.b16 {%0,%1}, [%2];"
        : "=r"(r[0]),"=r"(r[1]) : "r"(a));
}
__device__ __forceinline__ void ldsm_x2t(uint32_t a, uint32_t r[2]){
    asm volatile("ldmatrix.sync.aligned.m8n8.x2.trans.shared.b16 {%0,%1}, [%2];"
        : "=r"(r[0]),"=r"(r[1]) : "r"(a));
}
__device__ __forceinline__ void mma16816(float d[4], const uint32_t a[4], const uint32_t b[2]){
    asm volatile("mma.sync.aligned.m16n8k16.row.col.f32.bf16.bf16.f32 "
        "{%0,%1,%2,%3}, {%4,%5,%6,%7}, {%8,%9}, {%0,%1,%2,%3};"
        : "+f"(d[0]),"+f"(d[1]),"+f"(d[2]),"+f"(d[3])
        : "r"(a[0]),"r"(a[1]),"r"(a[2]),"r"(a[3]), "r"(b[0]),"r"(b[1]));
}

__device__ __forceinline__ void split2(float v, __nv_bfloat16& h, __nv_bfloat16& l){
    h = __float2bfloat16(v);
    l = __float2bfloat16(v - __bfloat162float(h));
}
// pack two floats into bf16x2 hi and lo (residual) words; low 16 bits = first arg
__device__ __forceinline__ void pack_hl(float p0, float p1, uint32_t& hi, uint32_t& lo){
    __nv_bfloat162 th, tl;
    th.x = __float2bfloat16(p0); th.y = __float2bfloat16(p1);
    tl.x = __float2bfloat16(p0 - __bfloat162float(th.x));
    tl.y = __float2bfloat16(p1 - __bfloat162float(th.y));
    hi = *reinterpret_cast<uint32_t*>(&th);
    lo = *reinterpret_cast<uint32_t*>(&tl);
}

// ================= bf16x3 mma.sync GEMM (128x128 tile) =================
#define KC      32
#define ROWSTR  80
#define TILEB   (128*ROWSTR)
#define STAGEB  (4*TILEB)
#define GSM     (2*STAGEB)

__device__ __forceinline__ void g_load_chunk(uint32_t sbase, int stage, int tid,
        const __nv_bfloat16* a0, const __nv_bfloat16* a1,
        const __nv_bfloat16* b0, const __nv_bfloat16* b1, int K, int koff){
    uint32_t st = sbase + stage*STAGEB;
    #pragma unroll
    for (int t = 0; t < 4; t++){
        const __nv_bfloat16* src = (t==0? a0 : t==1? a1 : t==2? b0 : b1);
        uint32_t tb = st + t*TILEB;
        #pragma unroll
        for (int s = 0; s < 2; s++){
            int idx = tid + s*256;
            int row = idx >> 2, seg = idx & 3;
            const __nv_bfloat16* g = src + (size_t)row*K + koff + seg*8;
            CP16(tb + row*ROWSTR + seg*16, g);
        }
    }
}

template<int ACT, int OUTB>
__global__ void __launch_bounds__(256)
tgemm_k(const __nv_bfloat16* __restrict__ Ah, const __nv_bfloat16* __restrict__ Al,
        const __nv_bfloat16* __restrict__ Bh, const __nv_bfloat16* __restrict__ Bl,
        const float* __restrict__ bias, const float* __restrict__ resid,
        float* __restrict__ C, __nv_bfloat16* __restrict__ Ch, __nv_bfloat16* __restrict__ Cl,
        int Nn, int K){
    extern __shared__ char smc[];
    uint32_t sb = _s2u(smc);
    int tid = threadIdx.x, wid = tid>>5, lane = tid&31;
    int wm = wid>>2, wn = wid&3;
    int bm = blockIdx.y*128, bn = blockIdx.x*128;

    const __nv_bfloat16* a0 = Ah + (size_t)bm*K;
    const __nv_bfloat16* a1 = Al + (size_t)bm*K;
    const __nv_bfloat16* b0 = Bh + (size_t)bn*K;
    const __nv_bfloat16* b1 = Bl + (size_t)bn*K;
    int nk = K/KC;

    float acc[4][4][4];
    #pragma unroll
    for (int i = 0; i < 4; i++){
        #pragma unroll
        for (int j = 0; j < 4; j++){
            #pragma unroll
            for (int q = 0; q < 4; q++) acc[i][j][q] = 0.f;
        }
    }

    g_load_chunk(sb, 0, tid, a0,a1,b0,b1, K, 0);
    CPCOMMIT();
    g_load_chunk(sb, 1, tid, a0,a1,b0,b1, K, KC);
    CPCOMMIT();

    int arow = (lane & 15);
    int akhi = (lane >> 4) * 8;
    int brow = (lane & 7);
    int bkhi = ((lane >> 3) & 1) * 8;

    for (int c = 0; c < nk; c++){
        if (c+1 < nk) { CPWAITG(1); } else { CPWAITG(0); }
        __syncthreads();
        uint32_t st = sb + (c&1)*STAGEB;
        uint32_t Abase = st + (wm*64 + arow)*ROWSTR;
        uint32_t Bbase = st + 2*TILEB + (wn*32 + brow)*ROWSTR;
        #pragma unroll
        for (int kk2 = 0; kk2 < 2; kk2++){
            int kca = (kk2*16 + akhi)*2;
            int kcb = (kk2*16 + bkhi)*2;
            uint32_t ah[4][4], al[4][4], bh[4][2], bl[4][2];
            #pragma unroll
            for (int mi = 0; mi < 4; mi++){
                uint32_t addr = Abase + mi*16*ROWSTR + kca;
                ldsm_x4(addr, ah[mi]);
                ldsm_x4(addr + TILEB, al[mi]);
            }
            #pragma unroll
            for (int ni = 0; ni < 4; ni++){
                uint32_t addr = Bbase + ni*8*ROWSTR + kcb;
                ldsm_x2(addr, bh[ni]);
                ldsm_x2(addr + TILEB, bl[ni]);
            }
            #pragma unroll
            for (int mi = 0; mi < 4; mi++){
                #pragma unroll
                for (int ni = 0; ni < 4; ni++){
                    mma16816(acc[mi][ni], ah[mi], bh[ni]);
                    mma16816(acc[mi][ni], ah[mi], bl[ni]);
                    mma16816(acc[mi][ni], al[mi], bh[ni]);
                }
            }
        }
        __syncthreads();
        if (c+2 < nk){
            g_load_chunk(sb, c&1, tid, a0,a1,b0,b1, K, (c+2)*KC);
            CPCOMMIT();
        }
    }

    int r_in = lane >> 2, c_in = (lane & 3)*2;
    #pragma unroll
    for (int mi = 0; mi < 4; mi++){
        #pragma unroll
        for (int ni = 0; ni < 4; ni++){
            int gr = bm + wm*64 + mi*16 + r_in;
            int gc = bn + wn*32 + ni*8 + c_in;
            float b0v = bias ? bias[gc]   : 0.f;
            float b1v = bias ? bias[gc+1] : 0.f;
            #pragma unroll
            for (int half = 0; half < 2; half++){
                int rr = gr + half*8;
                float v0 = acc[mi][ni][half*2+0] + b0v;
                float v1 = acc[mi][ni][half*2+1] + b1v;
                if (ACT == 1){
                    float u = v0; v0 = 0.5f*u*(1.f+tanhf(0.7978845608028654f*(u+0.044715f*u*u*u)));
                    u = v1;       v1 = 0.5f*u*(1.f+tanhf(0.7978845608028654f*(u+0.044715f*u*u*u)));
                }
                if (ACT == 2){ v0 *= 0.5f; v1 *= 0.5f; }
                if (resid){
                    v0 += resid[(size_t)rr*Nn + gc];
                    v1 += resid[(size_t)rr*Nn + gc + 1];
                }
                if (OUTB){
                    uint32_t hw, lw;
                    pack_hl(v0, v1, hw, lw);
                    *reinterpret_cast<uint32_t*>(&Ch[(size_t)rr*Nn + gc]) = hw;
                    *reinterpret_cast<uint32_t*>(&Cl[(size_t)rr*Nn + gc]) = lw;
                } else {
                    float2 o; o.x = v0; o.y = v1;
                    *(float2*)&C[(size_t)rr*Nn + gc] = o;
                }
            }
        }
    }
}

// ================= tgemm64: 64x128 CTA tile, compact smem, 3 CTAs/SM =================
// For N=768 GEMMs (192-CTA problem -> 384 CTAs). Warp tile 32x32, 8 warps (2m x 4n).
// Compact layout: tile stores 8-row x 16B ldmatrix atoms contiguously:
//   phys(row, seg) = (row>>3)*512 + seg*128 + (row&7)*16   (seg = 16B column index, 0..3)
#define T64A   4096                  // 64 rows * 64B
#define T64B   8192                  // 128 rows * 64B
#define STG64  (2*T64A + 2*T64B)     // 24576 per stage: Ah, Al, Bh, Bl
#define GSM64  (2*STG64)             // 49152

__device__ __forceinline__ void g_load64(uint32_t sbase, int stage, int tid,
        const __nv_bfloat16* a0, const __nv_bfloat16* a1,
        const __nv_bfloat16* b0, const __nv_bfloat16* b1, int K, int koff){
    uint32_t st = sbase + stage*STG64;
    // A tiles: 2 x 256 chunks; B tiles: 2 x 512 chunks; total 1536 chunks, 6 per thread
    #pragma unroll
    for (int j = 0; j < 6; j++){
        int idx = tid + j*256;               // 0..1535
        const __nv_bfloat16* src;
        uint32_t tb;
        int pos;
        if (idx < 512){
            int t = idx >> 8; pos = idx & 255;
            src = t ? a1 : a0;
            tb = st + t*T64A;
        } else {
            int idx2 = idx - 512;
            int t = idx2 >> 9; pos = idx2 & 511;
            src = t ? b1 : b0;
            tb = st + 2*T64A + t*T64B;
        }
        int row = pos >> 2, seg = pos & 3;
        const __nv_bfloat16* g = src + (size_t)row*K + koff + seg*8;
        CP16(tb + ((row>>3)<<9) + (seg<<7) + ((row&7)<<4), g);
    }
}

template<int ACT>
__global__ void __launch_bounds__(256, 3)
tgemm64_k(const __nv_bfloat16* __restrict__ Ah, const __nv_bfloat16* __restrict__ Al,
          const __nv_bfloat16* __restrict__ Bh, const __nv_bfloat16* __restrict__ Bl,
          const float* __restrict__ bias, const float* __restrict__ resid,
          float* __restrict__ C, int Nn, int K){
    extern __shared__ char smc[];
    uint32_t sb = _s2u(smc);
    int tid = threadIdx.x, wid = tid>>5, lane = tid&31;
    int wm = wid>>2, wn = wid&3;                 // 2m x 4n warps, warp tile 32x32
    int bm = blockIdx.y*64, bn = blockIdx.x*128;

    const __nv_bfloat16* a0 = Ah + (size_t)bm*K;
    const __nv_bfloat16* a1 = Al + (size_t)bm*K;
    const __nv_bfloat16* b0 = Bh + (size_t)bn*K;
    const __nv_bfloat16* b1 = Bl + (size_t)bn*K;
    int nk = K/KC;

    float acc[2][4][4];
    #pragma unroll
    for (int i = 0; i < 2; i++){
        #pragma unroll
        for (int j = 0; j < 4; j++){
            #pragma unroll
            for (int q = 0; q < 4; q++) acc[i][j][q] = 0.f;
        }
    }

    g_load64(sb, 0, tid, a0,a1,b0,b1, K, 0);
    CPCOMMIT();
    g_load64(sb, 1, tid, a0,a1,b0,b1, K, KC);
    CPCOMMIT();

    int arow = lane & 15;
    int ahalf = lane >> 4;                       // 16B col half 0/1
    int abyte = (arow & 7) << 4;
    int agrp  = wm*4 + (arow >> 3);              // 8-row group base for mi=0
    int brow  = lane & 7;
    int bhalf = (lane >> 3) & 1;
    int bgrp  = wn*4;

    for (int c = 0; c < nk; c++){
        if (c+1 < nk) { CPWAITG(1); } else { CPWAITG(0); }
        __syncthreads();
        uint32_t st = sb + (c&1)*STG64;
        #pragma unroll
        for (int kk2 = 0; kk2 < 2; kk2++){
            int sega = kk2*2 + ahalf;
            int segb = kk2*2 + bhalf;
            uint32_t ah[2][4], al[2][4], bh[4][2], bl[4][2];
            #pragma unroll
            for (int mi = 0; mi < 2; mi++){
                uint32_t addr = st + ((agrp + mi*2)<<9) + (sega<<7) + abyte;
                ldsm_x4(addr, ah[mi]);
                ldsm_x4(addr + T64A, al[mi]);
            }
            #pragma unroll
            for (int ni = 0; ni < 4; ni++){
                uint32_t addr = st + 2*T64A + ((bgrp + ni)<<9) + (segb<<7) + (brow<<4);
                ldsm_x2(addr, bh[ni]);
                ldsm_x2(addr + T64B, bl[ni]);
            }
            #pragma unroll
            for (int mi = 0; mi < 2; mi++){
                #pragma unroll
                for (int ni = 0; ni < 4; ni++){
                    mma16816(acc[mi][ni], ah[mi], bh[ni]);
                    mma16816(acc[mi][ni], ah[mi], bl[ni]);
                    mma16816(acc[mi][ni], al[mi], bh[ni]);
                }
            }
        }
        __syncthreads();
        if (c+2 < nk){
            g_load64(sb, c&1, tid, a0,a1,b0,b1, K, (c+2)*KC);
            CPCOMMIT();
        }
    }

    int r_in = lane >> 2, c_in = (lane & 3)*2;
    #pragma unroll
    for (int mi = 0; mi < 2; mi++){
        #pragma unroll
        for (int ni = 0; ni < 4; ni++){
            int gr = bm + wm*32 + mi*16 + r_in;
            int gc = bn + wn*32 + ni*8 + c_in;
            float b0v = bias ? bias[gc]   : 0.f;
            float b1v = bias ? bias[gc+1] : 0.f;
            #pragma unroll
            for (int half = 0; half < 2; half++){
                int rr = gr + half*8;
                float v0 = acc[mi][ni][half*2+0] + b0v;
                float v1 = acc[mi][ni][half*2+1] + b1v;
                if (ACT == 2){ v0 *= 0.5f; v1 *= 0.5f; }
                if (resid){
                    v0 += resid[(size_t)rr*Nn + gc];
                    v1 += resid[(size_t)rr*Nn + gc + 1];
                }
                float2 o; o.x = v0; o.y = v1;
                *(float2*)&C[(size_t)rr*Nn + gc] = o;
            }
        }
    }
}

// ---------------- fused transpose+split of ALL weights: one launch ----------------
__global__ void __launch_bounds__(256)
wsplit_all_k(const float* __restrict__ w0, const float* __restrict__ w1,
             const float* __restrict__ w2, const float* __restrict__ w3,
             const float* __restrict__ w4, const float* __restrict__ w5,
             const float* __restrict__ w6, const float* __restrict__ w7,
             __nv_bfloat16* __restrict__ hi, __nv_bfloat16* __restrict__ lo){
    const int   segStart[9] = {0,1728,2304,4608,6912,8064,8640,10944,13248};
    const int   segK[8]     = {768,768,768,3072,768,768,768,3072};
    const int   segN[8]     = {2304,768,3072,768,1536,768,3072,768};
    const size_t segDst[8]  = {0ul,1769472ul,2359296ul,4718592ul,7077888ul,8257536ul,8847360ul,11206656ul};

    int bid = blockIdx.x;
    int s = 0;
    #pragma unroll
    for (int i = 0; i < 8; i++) if (bid >= segStart[i+1]) s = i+1;
    const float* W;
    switch (s){
        case 0: W = w0; break; case 1: W = w1; break; case 2: W = w2; break;
        case 3: W = w3; break; case 4: W = w4; break; case 5: W = w5; break;
        case 6: W = w6; break; default: W = w7; break;
    }
    int K = segK[s], N = segN[s];
    int local = bid - segStart[s];
    int tilesN = N >> 5;
    int bn = (local % tilesN) << 5;
    int bk = (local / tilesN) << 5;

    __shared__ float tile[32][33];
    int tx = threadIdx.x & 31, ty = threadIdx.x >> 5;   // 32 x 8
    for (int i = ty; i < 32; i += 8) tile[i][tx] = W[(size_t)(bk+i)*N + bn+tx];
    __syncthreads();
    __nv_bfloat16* hseg = hi + segDst[s];
    __nv_bfloat16* lseg = lo + segDst[s];
    for (int i = ty; i < 32; i += 8){
        float v = tile[tx][i];                 // = W[bk+tx][bn+i]
        __nv_bfloat16 h, l; split2(v, h, l);
        size_t o = (size_t)(bn+i)*K + bk+tx;
        hseg[o]=h; lseg[o]=l;
    }
}

// ---------------- rope table ----------------
__global__ void rope_table_k(float* __restrict__ sins, float* __restrict__ coss){
    int idx = blockIdx.x*blockDim.x + threadIdx.x;
    if (idx >= KVL*32) return;
    int p = idx>>5, lane = idx&31;
    double inv = exp(-(double)lane * 0.28782313662425575);
    double sd, cd; sincos((double)p*inv, &sd, &cd);
    sins[idx]=(float)sd; coss[idx]=(float)cd;
}

// ---------------- rmsnorm -> bf16 hi/lo split ----------------
__global__ void rmsnorm_split_k(const float* __restrict__ x, const float* __restrict__ w,
                                __nv_bfloat16* __restrict__ hi, __nv_bfloat16* __restrict__ lo) {
    int r = blockIdx.x, tid = threadIdx.x;
    const float* xr = x + (size_t)r*DM;
    float ss = 0.f;
    for (int i = tid; i < DM; i += 256) { float v = xr[i]; ss += v*v; }
    __shared__ float red[256];
    red[tid] = ss; __syncthreads();
    for (int s = 128; s > 0; s >>= 1) { if (tid < s) red[tid] += red[tid+s]; __syncthreads(); }
    float rs = rsqrtf(red[0] * (1.f/DM) + EPS);
    for (int i = tid; i < DM; i += 256){
        float v = xr[i]*rs*w[i];
        __nv_bfloat16 h, l; split2(v, h, l);
        hi[(size_t)r*DM + i] = h; lo[(size_t)r*DM + i] = l;
    }
}

// ---------------- plain rmsnorm (final) ----------------
__global__ void rmsnorm_k(const float* __restrict__ x, const float* __restrict__ w,
                          float* __restrict__ y) {
    int r = blockIdx.x, tid = threadIdx.x;
    const float* xr = x + (size_t)r*DM;
    float ss = 0.f;
    for (int i = tid; i < DM; i += 256) { float v = xr[i]; ss += v*v; }
    __shared__ float red[256];
    red[tid] = ss; __syncthreads();
    for (int s = 128; s > 0; s >>= 1) { if (tid < s) red[tid] += red[tid+s]; __syncthreads(); }
    float rs = rsqrtf(red[0] * (1.f/DM) + EPS);
    float* yr = y + (size_t)r*DM;
    for (int i = tid; i < DM; i += 256) yr[i] = xr[i]*rs*w[i];
}

// ---------------- kv cache copy ----------------
__global__ void copy_cache_k(const float* __restrict__ cached, float* __restrict__ kvout) {
    int idx = blockIdx.x*blockDim.x + threadIdx.x;
    const int per = CCH*2*NH*HD;
    const int tot = BB*per;
    if (idx >= tot) return;
    int b = idx / per, r = idx % per;
    kvout[(size_t)b*KVL*2*NH*HD + r] = cached[idx];
}

// ---------------- qkv post: head rmsnorm, K/V -> cache, rope+scale+split Q ----------------
__global__ void qkv_post_k(const float* __restrict__ qkv, const float* __restrict__ qw,
                           const float* __restrict__ kw, float* __restrict__ kvout,
                           __nv_bfloat16* __restrict__ qsh, __nv_bfloat16* __restrict__ qsl,
                           const float* __restrict__ rs_, const float* __restrict__ rc_) {
    int w = (blockIdx.x*blockDim.x + threadIdx.x) >> 5;
    int lane = threadIdx.x & 31;
    if (w >= RR*NH) return;
    int b = w / (NN*NH), rem = w % (NN*NH);
    int n = rem / NH, h = rem % NH;
    const float* base = qkv + (size_t)(b*NN + n)*(3*NH*HD) + h*HD*3;
    float q0 = base[lane*3+0],      q1 = base[(lane+32)*3+0];
    float k0 = base[lane*3+1],      k1 = base[(lane+32)*3+1];
    float v0 = base[lane*3+2],      v1 = base[(lane+32)*3+2];
    float ssq = q0*q0 + q1*q1, ssk = k0*k0 + k1*k1;
    #pragma unroll
    for (int off = 16; off; off >>= 1) {
        ssq += __shfl_xor_sync(0xffffffffu, ssq, off);
        ssk += __shfl_xor_sync(0xffffffffu, ssk, off);
    }
    float rq = rsqrtf(ssq*(1.f/HD) + EPS);
    float rk = rsqrtf(ssk*(1.f/HD) + EPS);
    q0 *= rq*qw[lane]; q1 *= rq*qw[lane+32];
    k0 *= rk*kw[lane]; k1 *= rk*kw[lane+32];
    size_t ko = ((((size_t)b*KVL + CCH + n)*2 + 0)*NH + h)*HD;
    kvout[ko + lane] = k0;            kvout[ko + lane + 32] = k1;
    size_t vo = ko + (size_t)NH*HD;
    kvout[vo + lane] = v0;            kvout[vo + lane + 32] = v1;
    int ti = (CCH + n)*32 + lane;
    float s = rs_[ti], c = rc_[ti];
    float r0 = (q0*c - q1*s) * 0.125f;
    float r1 = (q1*c + q0*s) * 0.125f;
    size_t qo = (((size_t)b*NH + h)*NN + n)*HD;
    __nv_bfloat16 h0,l0,h1,l1;
    split2(r0,h0,l0); split2(r1,h1,l1);
    qsh[qo + lane] = h0;      qsl[qo + lane] = l0;
    qsh[qo + lane + 32] = h1; qsl[qo + lane + 32] = l1;
}

// ---------------- rope + split K, split V: kvout -> [b,h,p,d] bf16 hi/lo ----------------
__global__ void kvsplit_k(const float* __restrict__ kvout,
                          __nv_bfloat16* __restrict__ ksh, __nv_bfloat16* __restrict__ ksl,
                          __nv_bfloat16* __restrict__ vsh, __nv_bfloat16* __restrict__ vsl,
                          const float* __restrict__ rs_, const float* __restrict__ rc_) {
    int w = (blockIdx.x*blockDim.x + threadIdx.x) >> 5;
    int lane = threadIdx.x & 31;
    if (w >= BB*KVL*NH) return;
    int b = w / (KVL*NH), rem = w % (KVL*NH);
    int p = rem / NH, h = rem % NH;
    size_t ko = ((((size_t)b*KVL + p)*2 + 0)*NH + h)*HD;
    float k0 = kvout[ko + lane], k1 = kvout[ko + lane + 32];
    size_t vo = ko + (size_t)NH*HD;
    float v0 = kvout[vo + lane], v1 = kvout[vo + lane + 32];
    int ti = p*32 + lane;
    float s = rs_[ti], c = rc_[ti];
    float r0 = k0*c - k1*s;
    float r1 = k1*c + k0*s;
    size_t o = (((size_t)b*NH + h)*KVL + p)*HD;
    __nv_bfloat16 h0,l0,h1,l1;
    split2(r0,h0,l0); split2(r1,h1,l1);
    ksh[o + lane] = h0;      ksl[o + lane] = l0;
    ksh[o + lane + 32] = h1; ksl[o + lane + 32] = l1;
    split2(v0,h0,l0); split2(v1,h1,l1);
    vsh[o + lane] = h0;      vsl[o + lane] = l0;
    vsh[o + lane + 32] = h1; vsl[o + lane + 32] = l1;
}

// ================= flash attention with mma.sync (bf16 hi/lo) =================
#define FA_STRB 144
#define FA_TB   (64*FA_STRB)            // 9216 B per tile
#define FA_SQ   (2*FA_TB)               // Q region
#define FA_STG  (4*FA_TB)               // per stage (Kh,Kl,Vh,Vl)
#define FA_SMEM (FA_SQ + 2*FA_STG)      // 92160 B
#define FA_NT   (KVL/64)                // 40 kv tiles

__global__ void __launch_bounds__(128)
fa_mma_k(const __nv_bfloat16* __restrict__ Qh, const __nv_bfloat16* __restrict__ Ql,
         const __nv_bfloat16* __restrict__ Kh, const __nv_bfloat16* __restrict__ Kl,
         const __nv_bfloat16* __restrict__ Vh, const __nv_bfloat16* __restrict__ Vl,
         __nv_bfloat16* __restrict__ Oh, __nv_bfloat16* __restrict__ Ol){
    extern __shared__ char smc[];
    uint32_t sb = _s2u(smc);
    int qt = blockIdx.x, h = blockIdx.y, b = blockIdx.z;
    int tid = threadIdx.x, wid = tid>>5, lane = tid&31;

    size_t bh = (size_t)b*NH + h;
    const __nv_bfloat16* gqh = Qh + (bh*NN + qt*64)*HD;
    const __nv_bfloat16* gql = Ql + (bh*NN + qt*64)*HD;
    const __nv_bfloat16* gkh = Kh + bh*KVL*HD;
    const __nv_bfloat16* gkl = Kl + bh*KVL*HD;
    const __nv_bfloat16* gvh = Vh + bh*KVL*HD;
    const __nv_bfloat16* gvl = Vl + bh*KVL*HD;

    #pragma unroll
    for (int i = 0; i < 8; i++){
        int idx = tid + i*128;
        int t = idx >> 9, pos = idx & 511;
        int row = pos >> 3, seg = pos & 7;
        const __nv_bfloat16* g = (t ? gql : gqh) + (size_t)row*HD + seg*8;
        CP16(sb + t*FA_TB + row*FA_STRB + seg*16, g);
    }
    CPCOMMIT();
    {
        uint32_t st = sb + FA_SQ;
        #pragma unroll
        for (int i = 0; i < 16; i++){
            int idx = tid + i*128;
            int t = idx >> 9, pos = idx & 511;
            int row = pos >> 3, seg = pos & 7;
            const __nv_bfloat16* g = (t==0? gkh : t==1? gkl : t==2? gvh : gvl)
                                   + (size_t)row*HD + seg*8;
            CP16(st + t*FA_TB + row*FA_STRB + seg*16, g);
        }
        CPCOMMIT();
    }

    CPWAITG(1);
    __syncthreads();
    uint32_t qfh[4][4], qfl[4][4];
    {
        int arow = wid*16 + (lane & 15);
        int kc = (lane >> 4) * 8;
        #pragma unroll
        for (int kk = 0; kk < 4; kk++){
            uint32_t addr = sb + arow*FA_STRB + (kk*16 + kc)*2;
            ldsm_x4(addr, qfh[kk]);
            ldsm_x4(addr + FA_TB, qfl[kk]);
        }
    }

    float acc[8][4];
    #pragma unroll
    for (int j = 0; j < 8; j++){
        #pragma unroll
        for (int q = 0; q < 4; q++) acc[j][q] = 0.f;
    }
    float m0 = -1e30f, m1 = -1e30f, l0 = 0.f, l1 = 0.f;

    for (int it = 0; it < FA_NT; it++){
        if (it + 1 < FA_NT){
            uint32_t st = sb + FA_SQ + ((it+1)&1)*FA_STG;
            int p0 = (it+1)*64;
            #pragma unroll
            for (int i = 0; i < 16; i++){
                int idx = tid + i*128;
                int t = idx >> 9, pos = idx & 511;
                int row = pos >> 3, seg = pos & 7;
                const __nv_bfloat16* g = (t==0? gkh : t==1? gkl : t==2? gvh : gvl)
                                       + (size_t)(p0+row)*HD + seg*8;
                CP16(st + t*FA_TB + row*FA_STRB + seg*16, g);
            }
            CPCOMMIT();
        }
        if (it + 1 < FA_NT) { CPWAITG(1); } else { CPWAITG(0); }
        __syncthreads();

        uint32_t st = sb + FA_SQ + (it&1)*FA_STG;
        uint32_t smKh = st, smVh = st + 2*FA_TB;

        float s[8][4];
        int l16 = lane & 15;
        int brow = lane & 7;
        int bkc = ((lane >> 3) & 1) * 8;
        #pragma unroll
        for (int j = 0; j < 8; j++){
            #pragma unroll
            for (int q = 0; q < 4; q++) s[j][q] = 0.f;
            #pragma unroll
            for (int kk = 0; kk < 4; kk++){
                uint32_t addr = smKh + (j*8 + brow)*FA_STRB + (kk*16 + bkc)*2;
                uint32_t kbh[2], kbl[2];
                ldsm_x2(addr, kbh);
                ldsm_x2(addr + FA_TB, kbl);
                mma16816(s[j], qfh[kk], kbh);
                mma16816(s[j], qfh[kk], kbl);
                mma16816(s[j], qfl[kk], kbh);
            }
        }

        float mx0 = -1e30f, mx1 = -1e30f;
        #pragma unroll
        for (int j = 0; j < 8; j++){
            mx0 = fmaxf(mx0, fmaxf(s[j][0], s[j][1]));
            mx1 = fmaxf(mx1, fmaxf(s[j][2], s[j][3]));
        }
        #pragma unroll
        for (int off = 1; off < 4; off <<= 1){
            mx0 = fmaxf(mx0, __shfl_xor_sync(0xffffffffu, mx0, off));
            mx1 = fmaxf(mx1, __shfl_xor_sync(0xffffffffu, mx1, off));
        }
        float mn0 = fmaxf(m0, mx0), mn1 = fmaxf(m1, mx1);
        float c0 = __expf(m0 - mn0), c1 = __expf(m1 - mn1);
        m0 = mn0; m1 = mn1;
        l0 *= c0; l1 *= c1;
        #pragma unroll
        for (int j = 0; j < 8; j++){
            acc[j][0] *= c0; acc[j][1] *= c0;
            acc[j][2] *= c1; acc[j][3] *= c1;
        }
        uint32_t phi[8][2], plo[8][2];
        #pragma unroll
        for (int j = 0; j < 8; j++){
            float p0 = __expf(s[j][0] - mn0);
            float p1 = __expf(s[j][1] - mn0);
            float p2 = __expf(s[j][2] - mn1);
            float p3 = __expf(s[j][3] - mn1);
            l0 += p0 + p1; l1 += p2 + p3;
            pack_hl(p0, p1, phi[j][0], plo[j][0]);
            pack_hl(p2, p3, phi[j][1], plo[j][1]);
        }

        #pragma unroll
        for (int kk = 0; kk < 4; kk++){
            uint32_t pah[4] = { phi[2*kk][0], phi[2*kk][1], phi[2*kk+1][0], phi[2*kk+1][1] };
            uint32_t pal[4] = { plo[2*kk][0], plo[2*kk][1], plo[2*kk+1][0], plo[2*kk+1][1] };
            #pragma unroll
            for (int j = 0; j < 8; j++){
                uint32_t addr = smVh + (kk*16 + l16)*FA_STRB + j*8*2;
                uint32_t vbh[2], vbl[2];
                ldsm_x2t(addr, vbh);
                ldsm_x2t(addr + FA_TB, vbl);
                mma16816(acc[j], pah, vbh);
                mma16816(acc[j], pah, vbl);
                mma16816(acc[j], pal, vbh);
            }
        }
        __syncthreads();
    }

    #pragma unroll
    for (int off = 1; off < 4; off <<= 1){
        l0 += __shfl_xor_sync(0xffffffffu, l0, off);
        l1 += __shfl_xor_sync(0xffffffffu, l1, off);
    }
    float rl0 = 1.f / l0, rl1 = 1.f / l1;

    int q0r = qt*64 + wid*16 + (lane >> 2);
    int cc = (lane & 3)*2;
    #pragma unroll
    for (int j = 0; j < 8; j++){
        int col = h*HD + j*8 + cc;
        float o0 = acc[j][0]*rl0, o1 = acc[j][1]*rl0;
        uint32_t hw, lw; pack_hl(o0, o1, hw, lw);
        size_t off0 = (size_t)(b*NN + q0r)*DM + col;
        *reinterpret_cast<uint32_t*>(&Oh[off0]) = hw;
        *reinterpret_cast<uint32_t*>(&Ol[off0]) = lw;
        float o2 = acc[j][2]*rl1, o3 = acc[j][3]*rl1;
        pack_hl(o2, o3, hw, lw);
        size_t off1 = (size_t)(b*NN + q0r + 8)*DM + col;
        *reinterpret_cast<uint32_t*>(&Oh[off1]) = hw;
        *reinterpret_cast<uint32_t*>(&Ol[off1]) = lw;
    }
}

// ---------------- GLU ----------------
__global__ void glu_k(const float* __restrict__ in, float* __restrict__ out) {
    int idx = blockIdx.x*blockDim.x + threadIdx.x;
    if (idx >= RR*DM) return;
    int r = idx / DM, c = idx % DM;
    float a = in[(size_t)r*(2*DM) + c];
    float g = in[(size_t)r*(2*DM) + DM + c];
    out[idx] = a / (1.f + expf(-g));
}

// ---------------- depthwise conv: 8 outputs/thread, register sliding window ----------------
__global__ void __launch_bounds__(256)
dwconv8_k(const float* __restrict__ in, const float* __restrict__ w,
          const float* __restrict__ bias, float* __restrict__ out) {
    int n8 = blockIdx.x;
    int b  = blockIdx.y;
    int n0 = n8*8;
    const float* bin = in + (size_t)b*NN*DM;
    float* bout = out + (size_t)b*NN*DM;
    #pragma unroll
    for (int cc = 0; cc < 3; cc++){
        int c = threadIdx.x + cc*256;
        const float* wr = w + c*KSZ;
        float win[38];
        #pragma unroll
        for (int j = 0; j < 38; j++){
            int nn = n0 + j - (KSZ/2);
            win[j] = (nn >= 0 && nn < NN) ? bin[(size_t)nn*DM + c] : 0.f;
        }
        float bv = bias[c];
        float acc[8];
        #pragma unroll
        for (int i = 0; i < 8; i++) acc[i] = bv;
        #pragma unroll
        for (int t = 0; t < KSZ; t++){
            float wv = wr[t];
            #pragma unroll
            for (int i = 0; i < 8; i++) acc[i] += win[i+t]*wv;
        }
        #pragma unroll
        for (int i = 0; i < 8; i++) bout[(size_t)(n0+i)*DM + c] = acc[i];
    }
}

// ---------------- batchnorm stats pass1: coalesced partial sums ----------------
__global__ void __launch_bounds__(256)
bnstats1_k(const float* __restrict__ x, float* __restrict__ p1, float* __restrict__ p2) {
    int blk = blockIdx.x;
    int r0 = blk * (RR/BN_BLKS);
    #pragma unroll
    for (int cc = 0; cc < 3; cc++){
        int c = threadIdx.x + cc*256;
        float s = 0.f, s2 = 0.f;
        #pragma unroll 4
        for (int r = 0; r < RR/BN_BLKS; r++){
            float v = x[(size_t)(r0+r)*DM + c];
            s += v; s2 += v*v;
        }
        p1[(size_t)blk*DM + c] = s;
        p2[(size_t)blk*DM + c] = s2;
    }
}

// ---------------- batchnorm stats pass2 ----------------
__global__ void bnstats2_k(const float* __restrict__ p1, const float* __restrict__ p2,
                           float* __restrict__ mean, float* __restrict__ var) {
    int c = blockIdx.x*blockDim.x + threadIdx.x;
    if (c >= DM) return;
    float s = 0.f, s2 = 0.f;
    for (int b = 0; b < BN_BLKS; b++){
        s  += p1[(size_t)b*DM + c];
        s2 += p2[(size_t)b*DM + c];
    }
    float m = s * (1.f/RR);
    mean[c] = m;
    var[c] = s2 * (1.f/RR) - m*m;
}

// ---------------- batchnorm apply + swish -> bf16 hi/lo ----------------
__global__ void bnapply_split_k(const float* __restrict__ x, const float* __restrict__ mean,
                                const float* __restrict__ var, const float* __restrict__ g,
                                const float* __restrict__ b,
                                __nv_bfloat16* __restrict__ hi, __nv_bfloat16* __restrict__ lo) {
    int idx = blockIdx.x*blockDim.x + threadIdx.x;
    if (idx >= RR*DM) return;
    int c = idx % DM;
    float v = (x[idx] - mean[c]) * rsqrtf(var[c] + EPS) * g[c] + b[c];
    v = v / (1.f + expf(-v));
    __nv_bfloat16 h, l; split2(v, h, l);
    hi[idx] = h; lo[idx] = l;
}

// ---------------- launch ----------------
extern "C" void kernel_launch(void* const* d_in, const int* in_sizes, int n_in,
                              void* d_out, int out_size) {
    const float* x_in      = (const float*)d_in[0];
    const float* cached    = (const float*)d_in[4];
    const float* ff1_nw    = (const float*)d_in[5];
    const float* ff1_w1    = (const float*)d_in[6];
    const float* ff1_b1    = (const float*)d_in[7];
    const float* ff1_w2    = (const float*)d_in[8];
    const float* ff1_b2    = (const float*)d_in[9];
    const float* attn_nw   = (const float*)d_in[10];
    const float* qkv_w     = (const float*)d_in[11];
    const float* out_w     = (const float*)d_in[12];
    const float* q_nw      = (const float*)d_in[13];
    const float* k_nw      = (const float*)d_in[14];
    const float* conv_nw   = (const float*)d_in[15];
    const float* pw1_w     = (const float*)d_in[16];
    const float* pw1_b     = (const float*)d_in[17];
    const float* dw_w      = (const float*)d_in[18];
    const float* dw_b      = (const float*)d_in[19];
    const float* bn_g      = (const float*)d_in[20];
    const float* bn_b      = (const float*)d_in[21];
    const float* pw2_w     = (const float*)d_in[22];
    const float* pw2_b     = (const float*)d_in[23];
    const float* ff2_nw    = (const float*)d_in[24];
    const float* ff2_w1    = (const float*)d_in[25];
    const float* ff2_b1    = (const float*)d_in[26];
    const float* ff2_w2    = (const float*)d_in[27];
    const float* ff2_b2    = (const float*)d_in[28];
    const float* out_nw    = (const float*)d_in[29];

    float* outx  = (float*)d_out;
    float* kvout = outx + (size_t)RR*DM;

    float *x_, *ff_, *qkv_, *glu_, *dw_, *mean_, *var_, *rs_, *rc_, *bnp1_, *bnp2_;
    __nv_bfloat16 *wth_, *wtl_, *abh_, *abl_, *a1h_, *a1l_, *qsh_, *qsl_, *ksh_, *ksl_, *vsh_, *vsl_;
    cudaGetSymbolAddress((void**)&x_,    g_x);
    cudaGetSymbolAddress((void**)&ff_,   g_ff);
    cudaGetSymbolAddress((void**)&qkv_,  g_qkv);
    cudaGetSymbolAddress((void**)&glu_,  g_glu);
    cudaGetSymbolAddress((void**)&dw_,   g_dw);
    cudaGetSymbolAddress((void**)&mean_, g_mean);
    cudaGetSymbolAddress((void**)&var_,  g_var);
    cudaGetSymbolAddress((void**)&rs_,   g_rs);
    cudaGetSymbolAddress((void**)&rc_,   g_rc);
    cudaGetSymbolAddress((void**)&bnp1_, g_bnp1);
    cudaGetSymbolAddress((void**)&bnp2_, g_bnp2);
    cudaGetSymbolAddress((void**)&wth_,  g_wth);
    cudaGetSymbolAddress((void**)&wtl_,  g_wtl);
    cudaGetSymbolAddress((void**)&abh_,  g_abh);
    cudaGetSymbolAddress((void**)&abl_,  g_abl);
    cudaGetSymbolAddress((void**)&a1h_,  g_a1h);
    cudaGetSymbolAddress((void**)&a1l_,  g_a1l);
    cudaGetSymbolAddress((void**)&qsh_,  g_qsh);
    cudaGetSymbolAddress((void**)&qsl_,  g_qsl);
    cudaGetSymbolAddress((void**)&ksh_,  g_ksh);
    cudaGetSymbolAddress((void**)&ksl_,  g_ksl);
    cudaGetSymbolAddress((void**)&vsh_,  g_vsh);
    cudaGetSymbolAddress((void**)&vsl_,  g_vsl);

    static int attr_set = 0;
    if (!attr_set) {
        cudaFuncSetAttribute(fa_mma_k, cudaFuncAttributeMaxDynamicSharedMemorySize, FA_SMEM);
        cudaFuncSetAttribute(tgemm_k<0,0>, cudaFuncAttributeMaxDynamicSharedMemorySize, GSM);
        cudaFuncSetAttribute(tgemm_k<1,1>, cudaFuncAttributeMaxDynamicSharedMemorySize, GSM);
        cudaFuncSetAttribute(tgemm64_k<0>, cudaFuncAttributeMaxDynamicSharedMemorySize, GSM64);
        cudaFuncSetAttribute(tgemm64_k<2>, cudaFuncAttributeMaxDynamicSharedMemorySize, GSM64);
        attr_set = 1;
    }

    // weight offsets (transposed [N,K] layouts) — must match wsplit_all_k's segDst
    size_t o = 0;
    size_t off_qkv = o; o += (size_t)(3*NH*HD)*DM;
    size_t off_out = o; o += (size_t)DM*DM;
    size_t off_f1a = o; o += (size_t)FF*DM;
    size_t off_f1b = o; o += (size_t)DM*FF;
    size_t off_pw1 = o; o += (size_t)(2*DM)*DM;
    size_t off_pw2 = o; o += (size_t)DM*DM;
    size_t off_f2a = o; o += (size_t)FF*DM;
    size_t off_f2b = o; o += (size_t)DM*FF;

    wsplit_all_k<<<13248, 256>>>(qkv_w, out_w, ff1_w1, ff1_w2, pw1_w, pw2_w, ff2_w1, ff2_w2,
                                 wth_, wtl_);
    rope_table_k<<<(KVL*32 + 255)/256, 256>>>(rs_, rc_);

    cudaMemcpyAsync(x_, x_in, sizeof(float)*(size_t)RR*DM, cudaMemcpyDeviceToDevice, 0);

    const int EW = (RR*DM + 255)/256;

    // ---- FF1
    rmsnorm_split_k<<<RR, 256>>>(x_, ff1_nw, a1h_, a1l_);
    tgemm_k<1,1><<<dim3(FF/128, RR/128), 256, GSM>>>(a1h_, a1l_, wth_+off_f1a, wtl_+off_f1a,
                                                     ff1_b1, nullptr, nullptr, abh_, abl_, FF, DM);
    tgemm64_k<2><<<dim3(DM/128, RR/64), 256, GSM64>>>(abh_, abl_, wth_+off_f1b, wtl_+off_f1b,
                                                      ff1_b2, x_, x_, DM, FF);

    // ---- Attention
    rmsnorm_split_k<<<RR, 256>>>(x_, attn_nw, a1h_, a1l_);
    tgemm_k<0,0><<<dim3((3*NH*HD)/128, RR/128), 256, GSM>>>(a1h_, a1l_, wth_+off_qkv, wtl_+off_qkv,
                                                            nullptr, nullptr, qkv_, nullptr, nullptr,
                                                            3*NH*HD, DM);
    copy_cache_k<<<(BB*CCH*2*NH*HD + 255)/256, 256>>>(cached, kvout);
    qkv_post_k<<<RR*NH/4, 128>>>(qkv_, q_nw, k_nw, kvout, qsh_, qsl_, rs_, rc_);
    kvsplit_k<<<BB*KVL*NH/4, 128>>>(kvout, ksh_, ksl_, vsh_, vsl_, rs_, rc_);
    fa_mma_k<<<dim3(NN/64, NH, BB), 128, FA_SMEM>>>(qsh_, qsl_, ksh_, ksl_, vsh_, vsl_, a1h_, a1l_);
    tgemm64_k<0><<<dim3(DM/128, RR/64), 256, GSM64>>>(a1h_, a1l_, wth_+off_out, wtl_+off_out,
                                                      nullptr, x_, x_, DM, DM);

    // ---- Conv module
    rmsnorm_split_k<<<RR, 256>>>(x_, conv_nw, a1h_, a1l_);
    tgemm_k<0,0><<<dim3((2*DM)/128, RR/128), 256, GSM>>>(a1h_, a1l_, wth_+off_pw1, wtl_+off_pw1,
                                                         pw1_b, nullptr, ff_, nullptr, nullptr,
                                                         2*DM, DM);
    glu_k<<<EW, 256>>>(ff_, glu_);
    dwconv8_k<<<dim3(NN/8, BB), 256>>>(glu_, dw_w, dw_b, dw_);
    bnstats1_k<<<BN_BLKS, 256>>>(dw_, bnp1_, bnp2_);
    bnstats2_k<<<(DM + 255)/256, 256>>>(bnp1_, bnp2_, mean_, var_);
    bnapply_split_k<<<EW, 256>>>(dw_, mean_, var_, bn_g, bn_b, a1h_, a1l_);
    tgemm64_k<0><<<dim3(DM/128, RR/64), 256, GSM64>>>(a1h_, a1l_, wth_+off_pw2, wtl_+off_pw2,
                                                      pw2_b, nullptr, x_, DM, DM);

    // ---- FF2
    rmsnorm_split_k<<<RR, 256>>>(x_, ff2_nw, a1h_, a1l_);
    tgemm_k<1,1><<<dim3(FF/128, RR/128), 256, GSM>>>(a1h_, a1l_, wth_+off_f2a, wtl_+off_f2a,
                                                     ff2_b1, nullptr, nullptr, abh_, abl_, FF, DM);
    tgemm64_k<2><<<dim3(DM/128, RR/64), 256, GSM64>>>(abh_, abl_, wth_+off_f2b, wtl_+off_f2b,
                                                      ff2_b2, x_, x_, DM, FF);

    // ---- final rmsnorm -> output x
    rmsnorm_k<<<RR, 256>>>(x_, out_nw, outx);
}

// round 15
// speedup vs baseline: 1.0606x; 1.0606x over previous
#include <cuda_runtime.h>
#include <cuda_bf16.h>
#include <math.h>
#include <stdint.h>

// ---------------- problem constants ----------------
#define BB    2
#define NN    2048
#define CCH   512
#define KVL   2560          // CCH + NN
#define DM    768
#define NH    12
#define HD    64
#define FF    3072
#define KSZ   31
#define RR    (BB*NN)       // 4096 token rows
#define EPS   1e-5f

// ---------------- scratch (static device memory; no allocs) ----------------
__device__ float g_x   [RR*DM];
__device__ float g_ff  [RR*FF];          // fp32 GEMM outputs (pw1)
__device__ float g_qkv [RR*3*NH*HD];
__device__ float g_glu [RR*DM];
__device__ float g_dw  [RR*DM];
__device__ float g_mean[DM];
__device__ float g_var [DM];
__device__ float g_rs  [KVL*32];         // rope sin table
__device__ float g_rc  [KVL*32];         // rope cos table
#define BN_BLKS 128
__device__ float g_bnp1[BN_BLKS*DM];     // bn partial sums
__device__ float g_bnp2[BN_BLKS*DM];     // bn partial sumsq

#define WT_TOTAL 13565952
__device__ __align__(256) __nv_bfloat16 g_wth[WT_TOTAL];   // transposed weights hi
__device__ __align__(256) __nv_bfloat16 g_wtl[WT_TOTAL];   // transposed weights lo
__device__ __align__(256) __nv_bfloat16 g_abh[RR*FF];      // FF-wide activation hi
__device__ __align__(256) __nv_bfloat16 g_abl[RR*FF];      // FF-wide activation lo
__device__ __align__(256) __nv_bfloat16 g_a1h[RR*DM];      // DM-wide activation hi
__device__ __align__(256) __nv_bfloat16 g_a1l[RR*DM];      // DM-wide activation lo
__device__ __align__(256) __nv_bfloat16 g_qsh[RR*DM];      // Q split hi  [b,h,n,d] (scaled)
__device__ __align__(256) __nv_bfloat16 g_qsl[RR*DM];
#define KVE (BB*NH*KVL*HD)
__device__ __align__(256) __nv_bfloat16 g_ksh[KVE];        // roped K hi [b,h,p,d]
__device__ __align__(256) __nv_bfloat16 g_ksl[KVE];
__device__ __align__(256) __nv_bfloat16 g_vsh[KVE];        // V hi [b,h,p,d]
__device__ __align__(256) __nv_bfloat16 g_vsl[KVE];

// ================= PTX helpers (base sm_103-safe) ====
__device__ __forceinline__ uint32_t _s2u(const void* p){
    uint32_t a; asm("{ .reg .u64 t; cvta.to.shared.u64 t, %1; cvt.u32.u64 %0, t; }":"=r"(a):"l"(p)); return a;
}
#define CP16(d,s)   asm volatile("cp.async.cg.shared.global [%0], [%1], 16;"::"r"(d),"l"(s):"memory")
#define CPCOMMIT()  asm volatile("cp.async.commit_group;":::"memory")
#define CPWAITG(n)  asm volatile("cp.async.wait_group %0;"::"n"(n):"memory")

__device__ __forceinline__ void ldsm_x4(uint32_t a, uint32_t r[4]){
    asm volatile("ldmatrix.sync.aligned.m8n8.x4.shared.b16 {%0,%1,%2,%3}, [%4];"
        : "=r"(r[0]),"=r"(r[1]),"=r"(r[2]),"=r"(r[3]) : "r"(a));
}
__device__ __forceinline__ void ldsm_x2(uint32_t a, uint32_t r[2]){
    asm volatile("ldmatrix.sync.aligned.m8n8.x2.shared.b16 {%0,%1}, [%2];"
        : "=r"(r[0]),"=r"(r[1]) : "r"(a));
}
__device__ __forceinline__ void ldsm_x2t(uint32_t a, uint32_t r[2]){
    asm volatile("ldmatrix.sync.aligned.m8n8.x2.trans.shared.b16 {%0,%1}, [%2];"
        : "=r"(r[0]),"=r"(r[1]) : "r"(a));
}
__device__ __forceinline__ void mma16816(float d[4], const uint32_t a[4], const uint32_t b[2]){
    asm volatile("mma.sync.aligned.m16n8k16.row.col.f32.bf16.bf16.f32 "
        "{%0,%1,%2,%3}, {%4,%5,%6,%7}, {%8,%9}, {%0,%1,%2,%3};"
        : "+f"(d[0]),"+f"(d[1]),"+f"(d[2]),"+f"(d[3])
        : "r"(a[0]),"r"(a[1]),"r"(a[2]),"r"(a[3]), "r"(b[0]),"r"(b[1]));
}

__device__ __forceinline__ void split2(float v, __nv_bfloat16& h, __nv_bfloat16& l){
    h = __float2bfloat16(v);
    l = __float2bfloat16(v - __bfloat162float(h));
}
// pack two floats into bf16x2 hi and lo (residual) words; low 16 bits = first arg
__device__ __forceinline__ void pack_hl(float p0, float p1, uint32_t& hi, uint32_t& lo){
    __nv_bfloat162 th, tl;
    th.x = __float2bfloat16(p0); th.y = __float2bfloat16(p1);
    tl.x = __float2bfloat16(p0 - __bfloat162float(th.x));
    tl.y = __float2bfloat16(p1 - __bfloat162float(th.y));
    hi = *reinterpret_cast<uint32_t*>(&th);
    lo = *reinterpret_cast<uint32_t*>(&tl);
}

// ================= bf16x3 mma.sync GEMM =================
#define KC      32
#define ROWSTR  80
#define TILEB   (128*ROWSTR)
#define STAGEB  (4*TILEB)
#define GSM     (2*STAGEB)

__device__ __forceinline__ void g_load_chunk(uint32_t sbase, int stage, int tid,
        const __nv_bfloat16* a0, const __nv_bfloat16* a1,
        const __nv_bfloat16* b0, const __nv_bfloat16* b1, int K, int koff){
    uint32_t st = sbase + stage*STAGEB;
    #pragma unroll
    for (int t = 0; t < 4; t++){
        const __nv_bfloat16* src = (t==0? a0 : t==1? a1 : t==2? b0 : b1);
        uint32_t tb = st + t*TILEB;
        #pragma unroll
        for (int s = 0; s < 2; s++){
            int idx = tid + s*256;
            int row = idx >> 2, seg = idx & 3;
            const __nv_bfloat16* g = src + (size_t)row*K + koff + seg*8;
            CP16(tb + row*ROWSTR + seg*16, g);
        }
    }
}

template<int ACT, int OUTB>
__global__ void __launch_bounds__(256)
tgemm_k(const __nv_bfloat16* __restrict__ Ah, const __nv_bfloat16* __restrict__ Al,
        const __nv_bfloat16* __restrict__ Bh, const __nv_bfloat16* __restrict__ Bl,
        const float* __restrict__ bias, const float* __restrict__ resid,
        float* __restrict__ C, __nv_bfloat16* __restrict__ Ch, __nv_bfloat16* __restrict__ Cl,
        int Nn, int K){
    extern __shared__ char smc[];
    uint32_t sb = _s2u(smc);
    int tid = threadIdx.x, wid = tid>>5, lane = tid&31;
    int wm = wid>>2, wn = wid&3;
    int bm = blockIdx.y*128, bn = blockIdx.x*128;

    const __nv_bfloat16* a0 = Ah + (size_t)bm*K;
    const __nv_bfloat16* a1 = Al + (size_t)bm*K;
    const __nv_bfloat16* b0 = Bh + (size_t)bn*K;
    const __nv_bfloat16* b1 = Bl + (size_t)bn*K;
    int nk = K/KC;

    float acc[4][4][4];
    #pragma unroll
    for (int i = 0; i < 4; i++){
        #pragma unroll
        for (int j = 0; j < 4; j++){
            #pragma unroll
            for (int q = 0; q < 4; q++) acc[i][j][q] = 0.f;
        }
    }

    g_load_chunk(sb, 0, tid, a0,a1,b0,b1, K, 0);
    CPCOMMIT();
    g_load_chunk(sb, 1, tid, a0,a1,b0,b1, K, KC);
    CPCOMMIT();

    int arow = (lane & 15);
    int akhi = (lane >> 4) * 8;
    int brow = (lane & 7);
    int bkhi = ((lane >> 3) & 1) * 8;

    for (int c = 0; c < nk; c++){
        if (c+1 < nk) { CPWAITG(1); } else { CPWAITG(0); }
        __syncthreads();
        uint32_t st = sb + (c&1)*STAGEB;
        uint32_t Abase = st + (wm*64 + arow)*ROWSTR;
        uint32_t Bbase = st + 2*TILEB + (wn*32 + brow)*ROWSTR;
        #pragma unroll
        for (int kk2 = 0; kk2 < 2; kk2++){
            int kca = (kk2*16 + akhi)*2;
            int kcb = (kk2*16 + bkhi)*2;
            uint32_t ah[4][4], al[4][4], bh[4][2], bl[4][2];
            #pragma unroll
            for (int mi = 0; mi < 4; mi++){
                uint32_t addr = Abase + mi*16*ROWSTR + kca;
                ldsm_x4(addr, ah[mi]);
                ldsm_x4(addr + TILEB, al[mi]);
            }
            #pragma unroll
            for (int ni = 0; ni < 4; ni++){
                uint32_t addr = Bbase + ni*8*ROWSTR + kcb;
                ldsm_x2(addr, bh[ni]);
                ldsm_x2(addr + TILEB, bl[ni]);
            }
            #pragma unroll
            for (int mi = 0; mi < 4; mi++){
                #pragma unroll
                for (int ni = 0; ni < 4; ni++){
                    mma16816(acc[mi][ni], ah[mi], bh[ni]);
                    mma16816(acc[mi][ni], ah[mi], bl[ni]);
                    mma16816(acc[mi][ni], al[mi], bh[ni]);
                }
            }
        }
        __syncthreads();
        if (c+2 < nk){
            g_load_chunk(sb, c&1, tid, a0,a1,b0,b1, K, (c+2)*KC);
            CPCOMMIT();
        }
    }

    int r_in = lane >> 2, c_in = (lane & 3)*2;
    #pragma unroll
    for (int mi = 0; mi < 4; mi++){
        #pragma unroll
        for (int ni = 0; ni < 4; ni++){
            int gr = bm + wm*64 + mi*16 + r_in;
            int gc = bn + wn*32 + ni*8 + c_in;
            float b0v = bias ? bias[gc]   : 0.f;
            float b1v = bias ? bias[gc+1] : 0.f;
            #pragma unroll
            for (int half = 0; half < 2; half++){
                int rr = gr + half*8;
                float v0 = acc[mi][ni][half*2+0] + b0v;
                float v1 = acc[mi][ni][half*2+1] + b1v;
                if (ACT == 1){
                    float u = v0; v0 = 0.5f*u*(1.f+tanhf(0.7978845608028654f*(u+0.044715f*u*u*u)));
                    u = v1;       v1 = 0.5f*u*(1.f+tanhf(0.7978845608028654f*(u+0.044715f*u*u*u)));
                }
                if (ACT == 2){ v0 *= 0.5f; v1 *= 0.5f; }
                if (resid){
                    v0 += resid[(size_t)rr*Nn + gc];
                    v1 += resid[(size_t)rr*Nn + gc + 1];
                }
                if (OUTB){
                    uint32_t hw, lw;
                    pack_hl(v0, v1, hw, lw);
                    *reinterpret_cast<uint32_t*>(&Ch[(size_t)rr*Nn + gc]) = hw;
                    *reinterpret_cast<uint32_t*>(&Cl[(size_t)rr*Nn + gc]) = lw;
                } else {
                    float2 o; o.x = v0; o.y = v1;
                    *(float2*)&C[(size_t)rr*Nn + gc] = o;
                }
            }
        }
    }
}

// ---------------- fused transpose+split of ALL weights: one launch ----------------
__global__ void __launch_bounds__(256)
wsplit_all_k(const float* __restrict__ w0, const float* __restrict__ w1,
             const float* __restrict__ w2, const float* __restrict__ w3,
             const float* __restrict__ w4, const float* __restrict__ w5,
             const float* __restrict__ w6, const float* __restrict__ w7,
             __nv_bfloat16* __restrict__ hi, __nv_bfloat16* __restrict__ lo){
    const int   segStart[9] = {0,1728,2304,4608,6912,8064,8640,10944,13248};
    const int   segK[8]     = {768,768,768,3072,768,768,768,3072};
    const int   segN[8]     = {2304,768,3072,768,1536,768,3072,768};
    const size_t segDst[8]  = {0ul,1769472ul,2359296ul,4718592ul,7077888ul,8257536ul,8847360ul,11206656ul};

    int bid = blockIdx.x;
    int s = 0;
    #pragma unroll
    for (int i = 0; i < 8; i++) if (bid >= segStart[i+1]) s = i+1;
    const float* W;
    switch (s){
        case 0: W = w0; break; case 1: W = w1; break; case 2: W = w2; break;
        case 3: W = w3; break; case 4: W = w4; break; case 5: W = w5; break;
        case 6: W = w6; break; default: W = w7; break;
    }
    int K = segK[s], N = segN[s];
    int local = bid - segStart[s];
    int tilesN = N >> 5;
    int bn = (local % tilesN) << 5;
    int bk = (local / tilesN) << 5;

    __shared__ float tile[32][33];
    int tx = threadIdx.x & 31, ty = threadIdx.x >> 5;   // 32 x 8
    for (int i = ty; i < 32; i += 8) tile[i][tx] = W[(size_t)(bk+i)*N + bn+tx];
    __syncthreads();
    __nv_bfloat16* hseg = hi + segDst[s];
    __nv_bfloat16* lseg = lo + segDst[s];
    for (int i = ty; i < 32; i += 8){
        float v = tile[tx][i];                 // = W[bk+tx][bn+i]
        __nv_bfloat16 h, l; split2(v, h, l);
        size_t o = (size_t)(bn+i)*K + bk+tx;
        hseg[o]=h; lseg[o]=l;
    }
}

// ---------------- rope table ----------------
__global__ void rope_table_k(float* __restrict__ sins, float* __restrict__ coss){
    int idx = blockIdx.x*blockDim.x + threadIdx.x;
    if (idx >= KVL*32) return;
    int p = idx>>5, lane = idx&31;
    double inv = exp(-(double)lane * 0.28782313662425575);
    double sd, cd; sincos((double)p*inv, &sd, &cd);
    sins[idx]=(float)sd; coss[idx]=(float)cd;
}

// ---------------- rmsnorm -> bf16 hi/lo split ----------------
__global__ void rmsnorm_split_k(const float* __restrict__ x, const float* __restrict__ w,
                                __nv_bfloat16* __restrict__ hi, __nv_bfloat16* __restrict__ lo) {
    int r = blockIdx.x, tid = threadIdx.x;
    const float* xr = x + (size_t)r*DM;
    float ss = 0.f;
    for (int i = tid; i < DM; i += 256) { float v = xr[i]; ss += v*v; }
    __shared__ float red[256];
    red[tid] = ss; __syncthreads();
    for (int s = 128; s > 0; s >>= 1) { if (tid < s) red[tid] += red[tid+s]; __syncthreads(); }
    float rs = rsqrtf(red[0] * (1.f/DM) + EPS);
    for (int i = tid; i < DM; i += 256){
        float v = xr[i]*rs*w[i];
        __nv_bfloat16 h, l; split2(v, h, l);
        hi[(size_t)r*DM + i] = h; lo[(size_t)r*DM + i] = l;
    }
}

// ---------------- plain rmsnorm (final) ----------------
__global__ void rmsnorm_k(const float* __restrict__ x, const float* __restrict__ w,
                          float* __restrict__ y) {
    int r = blockIdx.x, tid = threadIdx.x;
    const float* xr = x + (size_t)r*DM;
    float ss = 0.f;
    for (int i = tid; i < DM; i += 256) { float v = xr[i]; ss += v*v; }
    __shared__ float red[256];
    red[tid] = ss; __syncthreads();
    for (int s = 128; s > 0; s >>= 1) { if (tid < s) red[tid] += red[tid+s]; __syncthreads(); }
    float rs = rsqrtf(red[0] * (1.f/DM) + EPS);
    float* yr = y + (size_t)r*DM;
    for (int i = tid; i < DM; i += 256) yr[i] = xr[i]*rs*w[i];
}

// ---------------- kv cache copy ----------------
__global__ void copy_cache_k(const float* __restrict__ cached, float* __restrict__ kvout) {
    int idx = blockIdx.x*blockDim.x + threadIdx.x;
    const int per = CCH*2*NH*HD;
    const int tot = BB*per;
    if (idx >= tot) return;
    int b = idx / per, r = idx % per;
    kvout[(size_t)b*KVL*2*NH*HD + r] = cached[idx];
}

// ---------------- qkv post: head rmsnorm, K/V -> cache, rope+scale+split Q ----------------
__global__ void qkv_post_k(const float* __restrict__ qkv, const float* __restrict__ qw,
                           const float* __restrict__ kw, float* __restrict__ kvout,
                           __nv_bfloat16* __restrict__ qsh, __nv_bfloat16* __restrict__ qsl,
                           const float* __restrict__ rs_, const float* __restrict__ rc_) {
    int w = (blockIdx.x*blockDim.x + threadIdx.x) >> 5;
    int lane = threadIdx.x & 31;
    if (w >= RR*NH) return;
    int b = w / (NN*NH), rem = w % (NN*NH);
    int n = rem / NH, h = rem % NH;
    const float* base = qkv + (size_t)(b*NN + n)*(3*NH*HD) + h*HD*3;
    float q0 = base[lane*3+0],      q1 = base[(lane+32)*3+0];
    float k0 = base[lane*3+1],      k1 = base[(lane+32)*3+1];
    float v0 = base[lane*3+2],      v1 = base[(lane+32)*3+2];
    float ssq = q0*q0 + q1*q1, ssk = k0*k0 + k1*k1;
    #pragma unroll
    for (int off = 16; off; off >>= 1) {
        ssq += __shfl_xor_sync(0xffffffffu, ssq, off);
        ssk += __shfl_xor_sync(0xffffffffu, ssk, off);
    }
    float rq = rsqrtf(ssq*(1.f/HD) + EPS);
    float rk = rsqrtf(ssk*(1.f/HD) + EPS);
    q0 *= rq*qw[lane]; q1 *= rq*qw[lane+32];
    k0 *= rk*kw[lane]; k1 *= rk*kw[lane+32];
    size_t ko = ((((size_t)b*KVL + CCH + n)*2 + 0)*NH + h)*HD;
    kvout[ko + lane] = k0;            kvout[ko + lane + 32] = k1;
    size_t vo = ko + (size_t)NH*HD;
    kvout[vo + lane] = v0;            kvout[vo + lane + 32] = v1;
    int ti = (CCH + n)*32 + lane;
    float s = rs_[ti], c = rc_[ti];
    float r0 = (q0*c - q1*s) * 0.125f;
    float r1 = (q1*c + q0*s) * 0.125f;
    size_t qo = (((size_t)b*NH + h)*NN + n)*HD;
    __nv_bfloat16 h0,l0,h1,l1;
    split2(r0,h0,l0); split2(r1,h1,l1);
    qsh[qo + lane] = h0;      qsl[qo + lane] = l0;
    qsh[qo + lane + 32] = h1; qsl[qo + lane + 32] = l1;
}

// ---------------- rope + split K, split V: kvout -> [b,h,p,d] bf16 hi/lo ----------------
__global__ void kvsplit_k(const float* __restrict__ kvout,
                          __nv_bfloat16* __restrict__ ksh, __nv_bfloat16* __restrict__ ksl,
                          __nv_bfloat16* __restrict__ vsh, __nv_bfloat16* __restrict__ vsl,
                          const float* __restrict__ rs_, const float* __restrict__ rc_) {
    int w = (blockIdx.x*blockDim.x + threadIdx.x) >> 5;
    int lane = threadIdx.x & 31;
    if (w >= BB*KVL*NH) return;
    int b = w / (KVL*NH), rem = w % (KVL*NH);
    int p = rem / NH, h = rem % NH;
    size_t ko = ((((size_t)b*KVL + p)*2 + 0)*NH + h)*HD;
    float k0 = kvout[ko + lane], k1 = kvout[ko + lane + 32];
    size_t vo = ko + (size_t)NH*HD;
    float v0 = kvout[vo + lane], v1 = kvout[vo + lane + 32];
    int ti = p*32 + lane;
    float s = rs_[ti], c = rc_[ti];
    float r0 = k0*c - k1*s;
    float r1 = k1*c + k0*s;
    size_t o = (((size_t)b*NH + h)*KVL + p)*HD;
    __nv_bfloat16 h0,l0,h1,l1;
    split2(r0,h0,l0); split2(r1,h1,l1);
    ksh[o + lane] = h0;      ksl[o + lane] = l0;
    ksh[o + lane + 32] = h1; ksl[o + lane + 32] = l1;
    split2(v0,h0,l0); split2(v1,h1,l1);
    vsh[o + lane] = h0;      vsl[o + lane] = l0;
    vsh[o + lane + 32] = h1; vsl[o + lane + 32] = l1;
}

// ================= flash attention with mma.sync (bf16 hi/lo) =================
#define FA_STRB 144
#define FA_TB   (64*FA_STRB)            // 9216 B per tile
#define FA_SQ   (2*FA_TB)               // Q region
#define FA_STG  (4*FA_TB)               // per stage (Kh,Kl,Vh,Vl)
#define FA_SMEM (FA_SQ + 2*FA_STG)      // 92160 B
#define FA_NT   (KVL/64)                // 40 kv tiles

__global__ void __launch_bounds__(128)
fa_mma_k(const __nv_bfloat16* __restrict__ Qh, const __nv_bfloat16* __restrict__ Ql,
         const __nv_bfloat16* __restrict__ Kh, const __nv_bfloat16* __restrict__ Kl,
         const __nv_bfloat16* __restrict__ Vh, const __nv_bfloat16* __restrict__ Vl,
         __nv_bfloat16* __restrict__ Oh, __nv_bfloat16* __restrict__ Ol){
    extern __shared__ char smc[];
    uint32_t sb = _s2u(smc);
    int qt = blockIdx.x, h = blockIdx.y, b = blockIdx.z;
    int tid = threadIdx.x, wid = tid>>5, lane = tid&31;

    size_t bh = (size_t)b*NH + h;
    const __nv_bfloat16* gqh = Qh + (bh*NN + qt*64)*HD;
    const __nv_bfloat16* gql = Ql + (bh*NN + qt*64)*HD;
    const __nv_bfloat16* gkh = Kh + bh*KVL*HD;
    const __nv_bfloat16* gkl = Kl + bh*KVL*HD;
    const __nv_bfloat16* gvh = Vh + bh*KVL*HD;
    const __nv_bfloat16* gvl = Vl + bh*KVL*HD;

    #pragma unroll
    for (int i = 0; i < 8; i++){
        int idx = tid + i*128;
        int t = idx >> 9, pos = idx & 511;
        int row = pos >> 3, seg = pos & 7;
        const __nv_bfloat16* g = (t ? gql : gqh) + (size_t)row*HD + seg*8;
        CP16(sb + t*FA_TB + row*FA_STRB + seg*16, g);
    }
    CPCOMMIT();
    {
        uint32_t st = sb + FA_SQ;
        #pragma unroll
        for (int i = 0; i < 16; i++){
            int idx = tid + i*128;
            int t = idx >> 9, pos = idx & 511;
            int row = pos >> 3, seg = pos & 7;
            const __nv_bfloat16* g = (t==0? gkh : t==1? gkl : t==2? gvh : gvl)
                                   + (size_t)row*HD + seg*8;
            CP16(st + t*FA_TB + row*FA_STRB + seg*16, g);
        }
        CPCOMMIT();
    }

    CPWAITG(1);
    __syncthreads();
    uint32_t qfh[4][4], qfl[4][4];
    {
        int arow = wid*16 + (lane & 15);
        int kc = (lane >> 4) * 8;
        #pragma unroll
        for (int kk = 0; kk < 4; kk++){
            uint32_t addr = sb + arow*FA_STRB + (kk*16 + kc)*2;
            ldsm_x4(addr, qfh[kk]);
            ldsm_x4(addr + FA_TB, qfl[kk]);
        }
    }

    float acc[8][4];
    #pragma unroll
    for (int j = 0; j < 8; j++){
        #pragma unroll
        for (int q = 0; q < 4; q++) acc[j][q] = 0.f;
    }
    float m0 = -1e30f, m1 = -1e30f, l0 = 0.f, l1 = 0.f;

    for (int it = 0; it < FA_NT; it++){
        if (it + 1 < FA_NT){
            uint32_t st = sb + FA_SQ + ((it+1)&1)*FA_STG;
            int p0 = (it+1)*64;
            #pragma unroll
            for (int i = 0; i < 16; i++){
                int idx = tid + i*128;
                int t = idx >> 9, pos = idx & 511;
                int row = pos >> 3, seg = pos & 7;
                const __nv_bfloat16* g = (t==0? gkh : t==1? gkl : t==2? gvh : gvl)
                                       + (size_t)(p0+row)*HD + seg*8;
                CP16(st + t*FA_TB + row*FA_STRB + seg*16, g);
            }
            CPCOMMIT();
        }
        if (it + 1 < FA_NT) { CPWAITG(1); } else { CPWAITG(0); }
        __syncthreads();

        uint32_t st = sb + FA_SQ + (it&1)*FA_STG;
        uint32_t smKh = st, smVh = st + 2*FA_TB;

        float s[8][4];
        int l16 = lane & 15;
        int brow = lane & 7;
        int bkc = ((lane >> 3) & 1) * 8;
        #pragma unroll
        for (int j = 0; j < 8; j++){
            #pragma unroll
            for (int q = 0; q < 4; q++) s[j][q] = 0.f;
            #pragma unroll
            for (int kk = 0; kk < 4; kk++){
                uint32_t addr = smKh + (j*8 + brow)*FA_STRB + (kk*16 + bkc)*2;
                uint32_t kbh[2], kbl[2];
                ldsm_x2(addr, kbh);
                ldsm_x2(addr + FA_TB, kbl);
                mma16816(s[j], qfh[kk], kbh);
                mma16816(s[j], qfh[kk], kbl);
                mma16816(s[j], qfl[kk], kbh);
            }
        }

        float mx0 = -1e30f, mx1 = -1e30f;
        #pragma unroll
        for (int j = 0; j < 8; j++){
            mx0 = fmaxf(mx0, fmaxf(s[j][0], s[j][1]));
            mx1 = fmaxf(mx1, fmaxf(s[j][2], s[j][3]));
        }
        #pragma unroll
        for (int off = 1; off < 4; off <<= 1){
            mx0 = fmaxf(mx0, __shfl_xor_sync(0xffffffffu, mx0, off));
            mx1 = fmaxf(mx1, __shfl_xor_sync(0xffffffffu, mx1, off));
        }
        float mn0 = fmaxf(m0, mx0), mn1 = fmaxf(m1, mx1);
        float c0 = __expf(m0 - mn0), c1 = __expf(m1 - mn1);
        m0 = mn0; m1 = mn1;
        l0 *= c0; l1 *= c1;
        #pragma unroll
        for (int j = 0; j < 8; j++){
            acc[j][0] *= c0; acc[j][1] *= c0;
            acc[j][2] *= c1; acc[j][3] *= c1;
        }
        uint32_t phi[8][2], plo[8][2];
        #pragma unroll
        for (int j = 0; j < 8; j++){
            float p0 = __expf(s[j][0] - mn0);
            float p1 = __expf(s[j][1] - mn0);
            float p2 = __expf(s[j][2] - mn1);
            float p3 = __expf(s[j][3] - mn1);
            l0 += p0 + p1; l1 += p2 + p3;
            pack_hl(p0, p1, phi[j][0], plo[j][0]);
            pack_hl(p2, p3, phi[j][1], plo[j][1]);
        }

        #pragma unroll
        for (int kk = 0; kk < 4; kk++){
            uint32_t pah[4] = { phi[2*kk][0], phi[2*kk][1], phi[2*kk+1][0], phi[2*kk+1][1] };
            uint32_t pal[4] = { plo[2*kk][0], plo[2*kk][1], plo[2*kk+1][0], plo[2*kk+1][1] };
            #pragma unroll
            for (int j = 0; j < 8; j++){
                uint32_t addr = smVh + (kk*16 + l16)*FA_STRB + j*8*2;
                uint32_t vbh[2], vbl[2];
                ldsm_x2t(addr, vbh);
                ldsm_x2t(addr + FA_TB, vbl);
                mma16816(acc[j], pah, vbh);
                mma16816(acc[j], pah, vbl);
                mma16816(acc[j], pal, vbh);
            }
        }
        __syncthreads();
    }

    #pragma unroll
    for (int off = 1; off < 4; off <<= 1){
        l0 += __shfl_xor_sync(0xffffffffu, l0, off);
        l1 += __shfl_xor_sync(0xffffffffu, l1, off);
    }
    float rl0 = 1.f / l0, rl1 = 1.f / l1;

    int q0r = qt*64 + wid*16 + (lane >> 2);
    int cc = (lane & 3)*2;
    #pragma unroll
    for (int j = 0; j < 8; j++){
        int col = h*HD + j*8 + cc;
        float o0 = acc[j][0]*rl0, o1 = acc[j][1]*rl0;
        uint32_t hw, lw; pack_hl(o0, o1, hw, lw);
        size_t off0 = (size_t)(b*NN + q0r)*DM + col;
        *reinterpret_cast<uint32_t*>(&Oh[off0]) = hw;
        *reinterpret_cast<uint32_t*>(&Ol[off0]) = lw;
        float o2 = acc[j][2]*rl1, o3 = acc[j][3]*rl1;
        pack_hl(o2, o3, hw, lw);
        size_t off1 = (size_t)(b*NN + q0r + 8)*DM + col;
        *reinterpret_cast<uint32_t*>(&Oh[off1]) = hw;
        *reinterpret_cast<uint32_t*>(&Ol[off1]) = lw;
    }
}

// ---------------- GLU ----------------
__global__ void glu_k(const float* __restrict__ in, float* __restrict__ out) {
    int idx = blockIdx.x*blockDim.x + threadIdx.x;
    if (idx >= RR*DM) return;
    int r = idx / DM, c = idx % DM;
    float a = in[(size_t)r*(2*DM) + c];
    float g = in[(size_t)r*(2*DM) + DM + c];
    out[idx] = a / (1.f + expf(-g));
}

// ---------------- depthwise conv: 8 outputs/thread, register sliding window ----------------
__global__ void __launch_bounds__(256)
dwconv8_k(const float* __restrict__ in, const float* __restrict__ w,
          const float* __restrict__ bias, float* __restrict__ out) {
    int n8 = blockIdx.x;
    int b  = blockIdx.y;
    int n0 = n8*8;
    const float* bin = in + (size_t)b*NN*DM;
    float* bout = out + (size_t)b*NN*DM;
    #pragma unroll
    for (int cc = 0; cc < 3; cc++){
        int c = threadIdx.x + cc*256;
        const float* wr = w + c*KSZ;
        float win[38];
        #pragma unroll
        for (int j = 0; j < 38; j++){
            int nn = n0 + j - (KSZ/2);
            win[j] = (nn >= 0 && nn < NN) ? bin[(size_t)nn*DM + c] : 0.f;
        }
        float bv = bias[c];
        float acc[8];
        #pragma unroll
        for (int i = 0; i < 8; i++) acc[i] = bv;
        #pragma unroll
        for (int t = 0; t < KSZ; t++){
            float wv = wr[t];
            #pragma unroll
            for (int i = 0; i < 8; i++) acc[i] += win[i+t]*wv;
        }
        #pragma unroll
        for (int i = 0; i < 8; i++) bout[(size_t)(n0+i)*DM + c] = acc[i];
    }
}

// ---------------- batchnorm stats pass1: coalesced partial sums ----------------
__global__ void __launch_bounds__(256)
bnstats1_k(const float* __restrict__ x, float* __restrict__ p1, float* __restrict__ p2) {
    int blk = blockIdx.x;
    int r0 = blk * (RR/BN_BLKS);
    #pragma unroll
    for (int cc = 0; cc < 3; cc++){
        int c = threadIdx.x + cc*256;
        float s = 0.f, s2 = 0.f;
        #pragma unroll 4
        for (int r = 0; r < RR/BN_BLKS; r++){
            float v = x[(size_t)(r0+r)*DM + c];
            s += v; s2 += v*v;
        }
        p1[(size_t)blk*DM + c] = s;
        p2[(size_t)blk*DM + c] = s2;
    }
}

// ---------------- batchnorm stats pass2 ----------------
__global__ void bnstats2_k(const float* __restrict__ p1, const float* __restrict__ p2,
                           float* __restrict__ mean, float* __restrict__ var) {
    int c = blockIdx.x*blockDim.x + threadIdx.x;
    if (c >= DM) return;
    float s = 0.f, s2 = 0.f;
    for (int b = 0; b < BN_BLKS; b++){
        s  += p1[(size_t)b*DM + c];
        s2 += p2[(size_t)b*DM + c];
    }
    float m = s * (1.f/RR);
    mean[c] = m;
    var[c] = s2 * (1.f/RR) - m*m;
}

// ---------------- batchnorm apply + swish -> bf16 hi/lo ----------------
__global__ void bnapply_split_k(const float* __restrict__ x, const float* __restrict__ mean,
                                const float* __restrict__ var, const float* __restrict__ g,
                                const float* __restrict__ b,
                                __nv_bfloat16* __restrict__ hi, __nv_bfloat16* __restrict__ lo) {
    int idx = blockIdx.x*blockDim.x + threadIdx.x;
    if (idx >= RR*DM) return;
    int c = idx % DM;
    float v = (x[idx] - mean[c]) * rsqrtf(var[c] + EPS) * g[c] + b[c];
    v = v / (1.f + expf(-v));
    __nv_bfloat16 h, l; split2(v, h, l);
    hi[idx] = h; lo[idx] = l;
}

// ---------------- launch ----------------
extern "C" void kernel_launch(void* const* d_in, const int* in_sizes, int n_in,
                              void* d_out, int out_size) {
    const float* x_in      = (const float*)d_in[0];
    const float* cached    = (const float*)d_in[4];
    const float* ff1_nw    = (const float*)d_in[5];
    const float* ff1_w1    = (const float*)d_in[6];
    const float* ff1_b1    = (const float*)d_in[7];
    const float* ff1_w2    = (const float*)d_in[8];
    const float* ff1_b2    = (const float*)d_in[9];
    const float* attn_nw   = (const float*)d_in[10];
    const float* qkv_w     = (const float*)d_in[11];
    const float* out_w     = (const float*)d_in[12];
    const float* q_nw      = (const float*)d_in[13];
    const float* k_nw      = (const float*)d_in[14];
    const float* conv_nw   = (const float*)d_in[15];
    const float* pw1_w     = (const float*)d_in[16];
    const float* pw1_b     = (const float*)d_in[17];
    const float* dw_w      = (const float*)d_in[18];
    const float* dw_b      = (const float*)d_in[19];
    const float* bn_g      = (const float*)d_in[20];
    const float* bn_b      = (const float*)d_in[21];
    const float* pw2_w     = (const float*)d_in[22];
    const float* pw2_b     = (const float*)d_in[23];
    const float* ff2_nw    = (const float*)d_in[24];
    const float* ff2_w1    = (const float*)d_in[25];
    const float* ff2_b1    = (const float*)d_in[26];
    const float* ff2_w2    = (const float*)d_in[27];
    const float* ff2_b2    = (const float*)d_in[28];
    const float* out_nw    = (const float*)d_in[29];

    float* outx  = (float*)d_out;
    float* kvout = outx + (size_t)RR*DM;

    float *x_, *ff_, *qkv_, *glu_, *dw_, *mean_, *var_, *rs_, *rc_, *bnp1_, *bnp2_;
    __nv_bfloat16 *wth_, *wtl_, *abh_, *abl_, *a1h_, *a1l_, *qsh_, *qsl_, *ksh_, *ksl_, *vsh_, *vsl_;
    cudaGetSymbolAddress((void**)&x_,    g_x);
    cudaGetSymbolAddress((void**)&ff_,   g_ff);
    cudaGetSymbolAddress((void**)&qkv_,  g_qkv);
    cudaGetSymbolAddress((void**)&glu_,  g_glu);
    cudaGetSymbolAddress((void**)&dw_,   g_dw);
    cudaGetSymbolAddress((void**)&mean_, g_mean);
    cudaGetSymbolAddress((void**)&var_,  g_var);
    cudaGetSymbolAddress((void**)&rs_,   g_rs);
    cudaGetSymbolAddress((void**)&rc_,   g_rc);
    cudaGetSymbolAddress((void**)&bnp1_, g_bnp1);
    cudaGetSymbolAddress((void**)&bnp2_, g_bnp2);
    cudaGetSymbolAddress((void**)&wth_,  g_wth);
    cudaGetSymbolAddress((void**)&wtl_,  g_wtl);
    cudaGetSymbolAddress((void**)&abh_,  g_abh);
    cudaGetSymbolAddress((void**)&abl_,  g_abl);
    cudaGetSymbolAddress((void**)&a1h_,  g_a1h);
    cudaGetSymbolAddress((void**)&a1l_,  g_a1l);
    cudaGetSymbolAddress((void**)&qsh_,  g_qsh);
    cudaGetSymbolAddress((void**)&qsl_,  g_qsl);
    cudaGetSymbolAddress((void**)&ksh_,  g_ksh);
    cudaGetSymbolAddress((void**)&ksl_,  g_ksl);
    cudaGetSymbolAddress((void**)&vsh_,  g_vsh);
    cudaGetSymbolAddress((void**)&vsl_,  g_vsl);

    static int attr_set = 0;
    if (!attr_set) {
        cudaFuncSetAttribute(fa_mma_k, cudaFuncAttributeMaxDynamicSharedMemorySize, FA_SMEM);
        cudaFuncSetAttribute(tgemm_k<0,0>, cudaFuncAttributeMaxDynamicSharedMemorySize, GSM);
        cudaFuncSetAttribute(tgemm_k<1,1>, cudaFuncAttributeMaxDynamicSharedMemorySize, GSM);
        cudaFuncSetAttribute(tgemm_k<2,0>, cudaFuncAttributeMaxDynamicSharedMemorySize, GSM);
        attr_set = 1;
    }

    // weight offsets (transposed [N,K] layouts) — must match wsplit_all_k's segDst
    size_t o = 0;
    size_t off_qkv = o; o += (size_t)(3*NH*HD)*DM;
    size_t off_out = o; o += (size_t)DM*DM;
    size_t off_f1a = o; o += (size_t)FF*DM;
    size_t off_f1b = o; o += (size_t)DM*FF;
    size_t off_pw1 = o; o += (size_t)(2*DM)*DM;
    size_t off_pw2 = o; o += (size_t)DM*DM;
    size_t off_f2a = o; o += (size_t)FF*DM;
    size_t off_f2b = o; o += (size_t)DM*FF;

    wsplit_all_k<<<13248, 256>>>(qkv_w, out_w, ff1_w1, ff1_w2, pw1_w, pw2_w, ff2_w1, ff2_w2,
                                 wth_, wtl_);
    rope_table_k<<<(KVL*32 + 255)/256, 256>>>(rs_, rc_);

    cudaMemcpyAsync(x_, x_in, sizeof(float)*(size_t)RR*DM, cudaMemcpyDeviceToDevice, 0);

    const int EW = (RR*DM + 255)/256;

    // ---- FF1
    rmsnorm_split_k<<<RR, 256>>>(x_, ff1_nw, a1h_, a1l_);
    tgemm_k<1,1><<<dim3(FF/128, RR/128), 256, GSM>>>(a1h_, a1l_, wth_+off_f1a, wtl_+off_f1a,
                                                     ff1_b1, nullptr, nullptr, abh_, abl_, FF, DM);
    tgemm_k<2,0><<<dim3(DM/128, RR/128), 256, GSM>>>(abh_, abl_, wth_+off_f1b, wtl_+off_f1b,
                                                     ff1_b2, x_, x_, nullptr, nullptr, DM, FF);

    // ---- Attention
    rmsnorm_split_k<<<RR, 256>>>(x_, attn_nw, a1h_, a1l_);
    tgemm_k<0,0><<<dim3((3*NH*HD)/128, RR/128), 256, GSM>>>(a1h_, a1l_, wth_+off_qkv, wtl_+off_qkv,
                                                            nullptr, nullptr, qkv_, nullptr, nullptr,
                                                            3*NH*HD, DM);
    copy_cache_k<<<(BB*CCH*2*NH*HD + 255)/256, 256>>>(cached, kvout);
    qkv_post_k<<<RR*NH/4, 128>>>(qkv_, q_nw, k_nw, kvout, qsh_, qsl_, rs_, rc_);
    kvsplit_k<<<BB*KVL*NH/4, 128>>>(kvout, ksh_, ksl_, vsh_, vsl_, rs_, rc_);
    fa_mma_k<<<dim3(NN/64, NH, BB), 128, FA_SMEM>>>(qsh_, qsl_, ksh_, ksl_, vsh_, vsl_, a1h_, a1l_);
    tgemm_k<0,0><<<dim3(DM/128, RR/128), 256, GSM>>>(a1h_, a1l_, wth_+off_out, wtl_+off_out,
                                                     nullptr, x_, x_, nullptr, nullptr, DM, DM);

    // ---- Conv module
    rmsnorm_split_k<<<RR, 256>>>(x_, conv_nw, a1h_, a1l_);
    tgemm_k<0,0><<<dim3((2*DM)/128, RR/128), 256, GSM>>>(a1h_, a1l_, wth_+off_pw1, wtl_+off_pw1,
                                                         pw1_b, nullptr, ff_, nullptr, nullptr,
                                                         2*DM, DM);
    glu_k<<<EW, 256>>>(ff_, glu_);
    dwconv8_k<<<dim3(NN/8, BB), 256>>>(glu_, dw_w, dw_b, dw_);
    bnstats1_k<<<BN_BLKS, 256>>>(dw_, bnp1_, bnp2_);
    bnstats2_k<<<(DM + 255)/256, 256>>>(bnp1_, bnp2_, mean_, var_);
    bnapply_split_k<<<EW, 256>>>(dw_, mean_, var_, bn_g, bn_b, a1h_, a1l_);
    tgemm_k<0,0><<<dim3(DM/128, RR/128), 256, GSM>>>(a1h_, a1l_, wth_+off_pw2, wtl_+off_pw2,
                                                     pw2_b, nullptr, x_, nullptr, nullptr, DM, DM);

    // ---- FF2
    rmsnorm_split_k<<<RR, 256>>>(x_, ff2_nw, a1h_, a1l_);
    tgemm_k<1,1><<<dim3(FF/128, RR/128), 256, GSM>>>(a1h_, a1l_, wth_+off_f2a, wtl_+off_f2a,
                                                     ff2_b1, nullptr, nullptr, abh_, abl_, FF, DM);
    tgemm_k<2,0><<<dim3(DM/128, RR/128), 256, GSM>>>(abh_, abl_, wth_+off_f2b, wtl_+off_f2b,
                                                     ff2_b2, x_, x_, nullptr, nullptr, DM, FF);

    // ---- final rmsnorm -> output x
    rmsnorm_k<<<RR, 256>>>(x_, out_nw, outx);
}

// round 16
// speedup vs baseline: 1.1428x; 1.0775x over previous
#include <cuda_runtime.h>
#include <cuda_bf16.h>
#include <math.h>
#include <stdint.h>

// ---------------- problem constants ----------------
#define BB    2
#define NN    2048
#define CCH   512
#define KVL   2560          // CCH + NN
#define DM    768
#define NH    12
#define HD    64
#define FF    3072
#define KSZ   31
#define RR    (BB*NN)       // 4096 token rows
#define EPS   1e-5f

// ---------------- scratch (static device memory; no allocs) ----------------
__device__ float g_x   [RR*DM];
__device__ float g_ff  [RR*FF];          // pw1 out; also split-K partials (2 x RR*DM fits)
__device__ float g_qkv [RR*3*NH*HD];
__device__ float g_glu [RR*DM];
__device__ float g_dw  [RR*DM];
__device__ float g_mean[DM];
__device__ float g_var [DM];
__device__ float g_rs  [KVL*32];         // rope sin table
__device__ float g_rc  [KVL*32];         // rope cos table
#define BN_BLKS 128
__device__ float g_bnp1[BN_BLKS*DM];     // bn partial sums
__device__ float g_bnp2[BN_BLKS*DM];     // bn partial sumsq

#define WT_TOTAL 13565952
__device__ __align__(256) __nv_bfloat16 g_wth[WT_TOTAL];   // transposed weights hi
__device__ __align__(256) __nv_bfloat16 g_wtl[WT_TOTAL];   // transposed weights lo
__device__ __align__(256) __nv_bfloat16 g_abh[RR*FF];      // FF-wide activation hi
__device__ __align__(256) __nv_bfloat16 g_abl[RR*FF];      // FF-wide activation lo
__device__ __align__(256) __nv_bfloat16 g_a1h[RR*DM];      // DM-wide activation hi
__device__ __align__(256) __nv_bfloat16 g_a1l[RR*DM];      // DM-wide activation lo
__device__ __align__(256) __nv_bfloat16 g_qsh[RR*DM];      // Q split hi  [b,h,n,d] (scaled)
__device__ __align__(256) __nv_bfloat16 g_qsl[RR*DM];
#define KVE (BB*NH*KVL*HD)
__device__ __align__(256) __nv_bfloat16 g_ksh[KVE];        // roped K hi [b,h,p,d]
__device__ __align__(256) __nv_bfloat16 g_ksl[KVE];
__device__ __align__(256) __nv_bfloat16 g_vsh[KVE];        // V hi [b,h,p,d]
__device__ __align__(256) __nv_bfloat16 g_vsl[KVE];

// ================= PTX helpers (base sm_103-safe) ====
__device__ __forceinline__ uint32_t _s2u(const void* p){
    uint32_t a; asm("{ .reg .u64 t; cvta.to.shared.u64 t, %1; cvt.u32.u64 %0, t; }":"=r"(a):"l"(p)); return a;
}
#define CP16(d,s)   asm volatile("cp.async.cg.shared.global [%0], [%1], 16;"::"r"(d),"l"(s):"memory")
#define CPCOMMIT()  asm volatile("cp.async.commit_group;":::"memory")
#define CPWAITG(n)  asm volatile("cp.async.wait_group %0;"::"n"(n):"memory")

__device__ __forceinline__ void ldsm_x4(uint32_t a, uint32_t r[4]){
    asm volatile("ldmatrix.sync.aligned.m8n8.x4.shared.b16 {%0,%1,%2,%3}, [%4];"
        : "=r"(r[0]),"=r"(r[1]),"=r"(r[2]),"=r"(r[3]) : "r"(a));
}
__device__ __forceinline__ void ldsm_x2(uint32_t a, uint32_t r[2]){
    asm volatile("ldmatrix.sync.aligned.m8n8.x2.shared.b16 {%0,%1}, [%2];"
        : "=r"(r[0]),"=r"(r[1]) : "r"(a));
}
__device__ __forceinline__ void ldsm_x2t(uint32_t a, uint32_t r[2]){
    asm volatile("ldmatrix.sync.aligned.m8n8.x2.trans.shared.b16 {%0,%1}, [%2];"
        : "=r"(r[0]),"=r"(r[1]) : "r"(a));
}
__device__ __forceinline__ void mma16816(float d[4], const uint32_t a[4], const uint32_t b[2]){
    asm volatile("mma.sync.aligned.m16n8k16.row.col.f32.bf16.bf16.f32 "
        "{%0,%1,%2,%3}, {%4,%5,%6,%7}, {%8,%9}, {%0,%1,%2,%3};"
        : "+f"(d[0]),"+f"(d[1]),"+f"(d[2]),"+f"(d[3])
        : "r"(a[0]),"r"(a[1]),"r"(a[2]),"r"(a[3]), "r"(b[0]),"r"(b[1]));
}

__device__ __forceinline__ void split2(float v, __nv_bfloat16& h, __nv_bfloat16& l){
    h = __float2bfloat16(v);
    l = __float2bfloat16(v - __bfloat162float(h));
}
// pack two floats into bf16x2 hi and lo (residual) words; low 16 bits = first arg
__device__ __forceinline__ void pack_hl(float p0, float p1, uint32_t& hi, uint32_t& lo){
    __nv_bfloat162 th, tl;
    th.x = __float2bfloat16(p0); th.y = __float2bfloat16(p1);
    tl.x = __float2bfloat16(p0 - __bfloat162float(th.x));
    tl.y = __float2bfloat16(p1 - __bfloat162float(th.y));
    hi = *reinterpret_cast<uint32_t*>(&th);
    lo = *reinterpret_cast<uint32_t*>(&tl);
}

// ================= bf16x3 mma.sync GEMM =================
#define KC      32
#define ROWSTR  80
#define TILEB   (128*ROWSTR)
#define STAGEB  (4*TILEB)
#define GSM     (2*STAGEB)

__device__ __forceinline__ void g_load_chunk(uint32_t sbase, int stage, int tid,
        const __nv_bfloat16* a0, const __nv_bfloat16* a1,
        const __nv_bfloat16* b0, const __nv_bfloat16* b1, int K, int koff){
    uint32_t st = sbase + stage*STAGEB;
    #pragma unroll
    for (int t = 0; t < 4; t++){
        const __nv_bfloat16* src = (t==0? a0 : t==1? a1 : t==2? b0 : b1);
        uint32_t tb = st + t*TILEB;
        #pragma unroll
        for (int s = 0; s < 2; s++){
            int idx = tid + s*256;
            int row = idx >> 2, seg = idx & 3;
            const __nv_bfloat16* g = src + (size_t)row*K + koff + seg*8;
            CP16(tb + row*ROWSTR + seg*16, g);
        }
    }
}

template<int ACT, int OUTB>
__global__ void __launch_bounds__(256)
tgemm_k(const __nv_bfloat16* __restrict__ Ah, const __nv_bfloat16* __restrict__ Al,
        const __nv_bfloat16* __restrict__ Bh, const __nv_bfloat16* __restrict__ Bl,
        const float* __restrict__ bias, const float* __restrict__ resid,
        float* __restrict__ C, __nv_bfloat16* __restrict__ Ch, __nv_bfloat16* __restrict__ Cl,
        int Nn, int K){
    extern __shared__ char smc[];
    uint32_t sb = _s2u(smc);
    int tid = threadIdx.x, wid = tid>>5, lane = tid&31;
    int wm = wid>>2, wn = wid&3;
    int bm = blockIdx.y*128, bn = blockIdx.x*128;

    const __nv_bfloat16* a0 = Ah + (size_t)bm*K;
    const __nv_bfloat16* a1 = Al + (size_t)bm*K;
    const __nv_bfloat16* b0 = Bh + (size_t)bn*K;
    const __nv_bfloat16* b1 = Bl + (size_t)bn*K;
    int nk = K/KC;

    float acc[4][4][4];
    #pragma unroll
    for (int i = 0; i < 4; i++){
        #pragma unroll
        for (int j = 0; j < 4; j++){
            #pragma unroll
            for (int q = 0; q < 4; q++) acc[i][j][q] = 0.f;
        }
    }

    g_load_chunk(sb, 0, tid, a0,a1,b0,b1, K, 0);
    CPCOMMIT();
    g_load_chunk(sb, 1, tid, a0,a1,b0,b1, K, KC);
    CPCOMMIT();

    int arow = (lane & 15);
    int akhi = (lane >> 4) * 8;
    int brow = (lane & 7);
    int bkhi = ((lane >> 3) & 1) * 8;

    for (int c = 0; c < nk; c++){
        if (c+1 < nk) { CPWAITG(1); } else { CPWAITG(0); }
        __syncthreads();
        uint32_t st = sb + (c&1)*STAGEB;
        uint32_t Abase = st + (wm*64 + arow)*ROWSTR;
        uint32_t Bbase = st + 2*TILEB + (wn*32 + brow)*ROWSTR;
        #pragma unroll
        for (int kk2 = 0; kk2 < 2; kk2++){
            int kca = (kk2*16 + akhi)*2;
            int kcb = (kk2*16 + bkhi)*2;
            uint32_t ah[4][4], al[4][4], bh[4][2], bl[4][2];
            #pragma unroll
            for (int mi = 0; mi < 4; mi++){
                uint32_t addr = Abase + mi*16*ROWSTR + kca;
                ldsm_x4(addr, ah[mi]);
                ldsm_x4(addr + TILEB, al[mi]);
            }
            #pragma unroll
            for (int ni = 0; ni < 4; ni++){
                uint32_t addr = Bbase + ni*8*ROWSTR + kcb;
                ldsm_x2(addr, bh[ni]);
                ldsm_x2(addr + TILEB, bl[ni]);
            }
            #pragma unroll
            for (int mi = 0; mi < 4; mi++){
                #pragma unroll
                for (int ni = 0; ni < 4; ni++){
                    mma16816(acc[mi][ni], ah[mi], bh[ni]);
                    mma16816(acc[mi][ni], ah[mi], bl[ni]);
                    mma16816(acc[mi][ni], al[mi], bh[ni]);
                }
            }
        }
        __syncthreads();
        if (c+2 < nk){
            g_load_chunk(sb, c&1, tid, a0,a1,b0,b1, K, (c+2)*KC);
            CPCOMMIT();
        }
    }

    int r_in = lane >> 2, c_in = (lane & 3)*2;
    #pragma unroll
    for (int mi = 0; mi < 4; mi++){
        #pragma unroll
        for (int ni = 0; ni < 4; ni++){
            int gr = bm + wm*64 + mi*16 + r_in;
            int gc = bn + wn*32 + ni*8 + c_in;
            float b0v = bias ? bias[gc]   : 0.f;
            float b1v = bias ? bias[gc+1] : 0.f;
            #pragma unroll
            for (int half = 0; half < 2; half++){
                int rr = gr + half*8;
                float v0 = acc[mi][ni][half*2+0] + b0v;
                float v1 = acc[mi][ni][half*2+1] + b1v;
                if (ACT == 1){
                    float u = v0; v0 = 0.5f*u*(1.f+tanhf(0.7978845608028654f*(u+0.044715f*u*u*u)));
                    u = v1;       v1 = 0.5f*u*(1.f+tanhf(0.7978845608028654f*(u+0.044715f*u*u*u)));
                }
                if (ACT == 2){ v0 *= 0.5f; v1 *= 0.5f; }
                if (resid){
                    v0 += resid[(size_t)rr*Nn + gc];
                    v1 += resid[(size_t)rr*Nn + gc + 1];
                }
                if (OUTB){
                    uint32_t hw, lw;
                    pack_hl(v0, v1, hw, lw);
                    *reinterpret_cast<uint32_t*>(&Ch[(size_t)rr*Nn + gc]) = hw;
                    *reinterpret_cast<uint32_t*>(&Cl[(size_t)rr*Nn + gc]) = lw;
                } else {
                    float2 o; o.x = v0; o.y = v1;
                    *(float2*)&C[(size_t)rr*Nn + gc] = o;
                }
            }
        }
    }
}

// ================= split-K variant: blockIdx.z picks K-half, writes fp32 partial =================
// Same 128x128 tile and mainloop as tgemm_k; no bias/act/resid; P[z] = A[:,zK/2:(z+1)K/2] * B-half.
__global__ void __launch_bounds__(256)
tgemm_sk_k(const __nv_bfloat16* __restrict__ Ah, const __nv_bfloat16* __restrict__ Al,
           const __nv_bfloat16* __restrict__ Bh, const __nv_bfloat16* __restrict__ Bl,
           float* __restrict__ P, int Nn, int K){
    extern __shared__ char smc[];
    uint32_t sb = _s2u(smc);
    int tid = threadIdx.x, wid = tid>>5, lane = tid&31;
    int wm = wid>>2, wn = wid&3;
    int bm = blockIdx.y*128, bn = blockIdx.x*128;
    int bz = blockIdx.z;
    int Klen = K >> 1;
    int kbase = bz * Klen;

    const __nv_bfloat16* a0 = Ah + (size_t)bm*K;
    const __nv_bfloat16* a1 = Al + (size_t)bm*K;
    const __nv_bfloat16* b0 = Bh + (size_t)bn*K;
    const __nv_bfloat16* b1 = Bl + (size_t)bn*K;
    int nk = Klen/KC;

    float acc[4][4][4];
    #pragma unroll
    for (int i = 0; i < 4; i++){
        #pragma unroll
        for (int j = 0; j < 4; j++){
            #pragma unroll
            for (int q = 0; q < 4; q++) acc[i][j][q] = 0.f;
        }
    }

    g_load_chunk(sb, 0, tid, a0,a1,b0,b1, K, kbase);
    CPCOMMIT();
    g_load_chunk(sb, 1, tid, a0,a1,b0,b1, K, kbase + KC);
    CPCOMMIT();

    int arow = (lane & 15);
    int akhi = (lane >> 4) * 8;
    int brow = (lane & 7);
    int bkhi = ((lane >> 3) & 1) * 8;

    for (int c = 0; c < nk; c++){
        if (c+1 < nk) { CPWAITG(1); } else { CPWAITG(0); }
        __syncthreads();
        uint32_t st = sb + (c&1)*STAGEB;
        uint32_t Abase = st + (wm*64 + arow)*ROWSTR;
        uint32_t Bbase = st + 2*TILEB + (wn*32 + brow)*ROWSTR;
        #pragma unroll
        for (int kk2 = 0; kk2 < 2; kk2++){
            int kca = (kk2*16 + akhi)*2;
            int kcb = (kk2*16 + bkhi)*2;
            uint32_t ah[4][4], al[4][4], bh[4][2], bl[4][2];
            #pragma unroll
            for (int mi = 0; mi < 4; mi++){
                uint32_t addr = Abase + mi*16*ROWSTR + kca;
                ldsm_x4(addr, ah[mi]);
                ldsm_x4(addr + TILEB, al[mi]);
            }
            #pragma unroll
            for (int ni = 0; ni < 4; ni++){
                uint32_t addr = Bbase + ni*8*ROWSTR + kcb;
                ldsm_x2(addr, bh[ni]);
                ldsm_x2(addr + TILEB, bl[ni]);
            }
            #pragma unroll
            for (int mi = 0; mi < 4; mi++){
                #pragma unroll
                for (int ni = 0; ni < 4; ni++){
                    mma16816(acc[mi][ni], ah[mi], bh[ni]);
                    mma16816(acc[mi][ni], ah[mi], bl[ni]);
                    mma16816(acc[mi][ni], al[mi], bh[ni]);
                }
            }
        }
        __syncthreads();
        if (c+2 < nk){
            g_load_chunk(sb, c&1, tid, a0,a1,b0,b1, K, kbase + (c+2)*KC);
            CPCOMMIT();
        }
    }

    float* Pz = P + (size_t)bz*RR*DM;
    int r_in = lane >> 2, c_in = (lane & 3)*2;
    #pragma unroll
    for (int mi = 0; mi < 4; mi++){
        #pragma unroll
        for (int ni = 0; ni < 4; ni++){
            int gr = bm + wm*64 + mi*16 + r_in;
            int gc = bn + wn*32 + ni*8 + c_in;
            #pragma unroll
            for (int half = 0; half < 2; half++){
                int rr = gr + half*8;
                float2 o; o.x = acc[mi][ni][half*2+0]; o.y = acc[mi][ni][half*2+1];
                *(float2*)&Pz[(size_t)rr*Nn + gc] = o;
            }
        }
    }
}

// combine split-K partials: out = 0.5*(p0+p1+bias) + resid  (in-place on resid buffer ok)
__global__ void comb_half_k(const float* __restrict__ P, const float* __restrict__ bias,
                            const float* __restrict__ resid, float* __restrict__ out){
    int idx = blockIdx.x*blockDim.x + threadIdx.x;
    if (idx >= RR*DM) return;
    int c = idx % DM;
    float v = 0.5f*(P[idx] + P[(size_t)RR*DM + idx] + bias[c]) + resid[idx];
    out[idx] = v;
}

// ---------------- fused transpose+split of ALL weights: one launch ----------------
__global__ void __launch_bounds__(256)
wsplit_all_k(const float* __restrict__ w0, const float* __restrict__ w1,
             const float* __restrict__ w2, const float* __restrict__ w3,
             const float* __restrict__ w4, const float* __restrict__ w5,
             const float* __restrict__ w6, const float* __restrict__ w7,
             __nv_bfloat16* __restrict__ hi, __nv_bfloat16* __restrict__ lo){
    const int   segStart[9] = {0,1728,2304,4608,6912,8064,8640,10944,13248};
    const int   segK[8]     = {768,768,768,3072,768,768,768,3072};
    const int   segN[8]     = {2304,768,3072,768,1536,768,3072,768};
    const size_t segDst[8]  = {0ul,1769472ul,2359296ul,4718592ul,7077888ul,8257536ul,8847360ul,11206656ul};

    int bid = blockIdx.x;
    int s = 0;
    #pragma unroll
    for (int i = 0; i < 8; i++) if (bid >= segStart[i+1]) s = i+1;
    const float* W;
    switch (s){
        case 0: W = w0; break; case 1: W = w1; break; case 2: W = w2; break;
        case 3: W = w3; break; case 4: W = w4; break; case 5: W = w5; break;
        case 6: W = w6; break; default: W = w7; break;
    }
    int K = segK[s], N = segN[s];
    int local = bid - segStart[s];
    int tilesN = N >> 5;
    int bn = (local % tilesN) << 5;
    int bk = (local / tilesN) << 5;

    __shared__ float tile[32][33];
    int tx = threadIdx.x & 31, ty = threadIdx.x >> 5;   // 32 x 8
    for (int i = ty; i < 32; i += 8) tile[i][tx] = W[(size_t)(bk+i)*N + bn+tx];
    __syncthreads();
    __nv_bfloat16* hseg = hi + segDst[s];
    __nv_bfloat16* lseg = lo + segDst[s];
    for (int i = ty; i < 32; i += 8){
        float v = tile[tx][i];                 // = W[bk+tx][bn+i]
        __nv_bfloat16 h, l; split2(v, h, l);
        size_t o = (size_t)(bn+i)*K + bk+tx;
        hseg[o]=h; lseg[o]=l;
    }
}

// ---------------- rope table ----------------
__global__ void rope_table_k(float* __restrict__ sins, float* __restrict__ coss){
    int idx = blockIdx.x*blockDim.x + threadIdx.x;
    if (idx >= KVL*32) return;
    int p = idx>>5, lane = idx&31;
    double inv = exp(-(double)lane * 0.28782313662425575);
    double sd, cd; sincos((double)p*inv, &sd, &cd);
    sins[idx]=(float)sd; coss[idx]=(float)cd;
}

// ---------------- rmsnorm -> bf16 hi/lo split ----------------
__global__ void rmsnorm_split_k(const float* __restrict__ x, const float* __restrict__ w,
                                __nv_bfloat16* __restrict__ hi, __nv_bfloat16* __restrict__ lo) {
    int r = blockIdx.x, tid = threadIdx.x;
    const float* xr = x + (size_t)r*DM;
    float ss = 0.f;
    for (int i = tid; i < DM; i += 256) { float v = xr[i]; ss += v*v; }
    __shared__ float red[256];
    red[tid] = ss; __syncthreads();
    for (int s = 128; s > 0; s >>= 1) { if (tid < s) red[tid] += red[tid+s]; __syncthreads(); }
    float rs = rsqrtf(red[0] * (1.f/DM) + EPS);
    for (int i = tid; i < DM; i += 256){
        float v = xr[i]*rs*w[i];
        __nv_bfloat16 h, l; split2(v, h, l);
        hi[(size_t)r*DM + i] = h; lo[(size_t)r*DM + i] = l;
    }
}

// ---------------- plain rmsnorm (final) ----------------
__global__ void rmsnorm_k(const float* __restrict__ x, const float* __restrict__ w,
                          float* __restrict__ y) {
    int r = blockIdx.x, tid = threadIdx.x;
    const float* xr = x + (size_t)r*DM;
    float ss = 0.f;
    for (int i = tid; i < DM; i += 256) { float v = xr[i]; ss += v*v; }
    __shared__ float red[256];
    red[tid] = ss; __syncthreads();
    for (int s = 128; s > 0; s >>= 1) { if (tid < s) red[tid] += red[tid+s]; __syncthreads(); }
    float rs = rsqrtf(red[0] * (1.f/DM) + EPS);
    float* yr = y + (size_t)r*DM;
    for (int i = tid; i < DM; i += 256) yr[i] = xr[i]*rs*w[i];
}

// ---------------- kv cache copy ----------------
__global__ void copy_cache_k(const float* __restrict__ cached, float* __restrict__ kvout) {
    int idx = blockIdx.x*blockDim.x + threadIdx.x;
    const int per = CCH*2*NH*HD;
    const int tot = BB*per;
    if (idx >= tot) return;
    int b = idx / per, r = idx % per;
    kvout[(size_t)b*KVL*2*NH*HD + r] = cached[idx];
}

// ---------------- qkv post: head rmsnorm, K/V -> cache, rope+scale+split Q ----------------
__global__ void qkv_post_k(const float* __restrict__ qkv, const float* __restrict__ qw,
                           const float* __restrict__ kw, float* __restrict__ kvout,
                           __nv_bfloat16* __restrict__ qsh, __nv_bfloat16* __restrict__ qsl,
                           const float* __restrict__ rs_, const float* __restrict__ rc_) {
    int w = (blockIdx.x*blockDim.x + threadIdx.x) >> 5;
    int lane = threadIdx.x & 31;
    if (w >= RR*NH) return;
    int b = w / (NN*NH), rem = w % (NN*NH);
    int n = rem / NH, h = rem % NH;
    const float* base = qkv + (size_t)(b*NN + n)*(3*NH*HD) + h*HD*3;
    float q0 = base[lane*3+0],      q1 = base[(lane+32)*3+0];
    float k0 = base[lane*3+1],      k1 = base[(lane+32)*3+1];
    float v0 = base[lane*3+2],      v1 = base[(lane+32)*3+2];
    float ssq = q0*q0 + q1*q1, ssk = k0*k0 + k1*k1;
    #pragma unroll
    for (int off = 16; off; off >>= 1) {
        ssq += __shfl_xor_sync(0xffffffffu, ssq, off);
        ssk += __shfl_xor_sync(0xffffffffu, ssk, off);
    }
    float rq = rsqrtf(ssq*(1.f/HD) + EPS);
    float rk = rsqrtf(ssk*(1.f/HD) + EPS);
    q0 *= rq*qw[lane]; q1 *= rq*qw[lane+32];
    k0 *= rk*kw[lane]; k1 *= rk*kw[lane+32];
    size_t ko = ((((size_t)b*KVL + CCH + n)*2 + 0)*NH + h)*HD;
    kvout[ko + lane] = k0;            kvout[ko + lane + 32] = k1;
    size_t vo = ko + (size_t)NH*HD;
    kvout[vo + lane] = v0;            kvout[vo + lane + 32] = v1;
    int ti = (CCH + n)*32 + lane;
    float s = rs_[ti], c = rc_[ti];
    float r0 = (q0*c - q1*s) * 0.125f;
    float r1 = (q1*c + q0*s) * 0.125f;
    size_t qo = (((size_t)b*NH + h)*NN + n)*HD;
    __nv_bfloat16 h0,l0,h1,l1;
    split2(r0,h0,l0); split2(r1,h1,l1);
    qsh[qo + lane] = h0;      qsl[qo + lane] = l0;
    qsh[qo + lane + 32] = h1; qsl[qo + lane + 32] = l1;
}

// ---------------- rope + split K, split V: kvout -> [b,h,p,d] bf16 hi/lo ----------------
__global__ void kvsplit_k(const float* __restrict__ kvout,
                          __nv_bfloat16* __restrict__ ksh, __nv_bfloat16* __restrict__ ksl,
                          __nv_bfloat16* __restrict__ vsh, __nv_bfloat16* __restrict__ vsl,
                          const float* __restrict__ rs_, const float* __restrict__ rc_) {
    int w = (blockIdx.x*blockDim.x + threadIdx.x) >> 5;
    int lane = threadIdx.x & 31;
    if (w >= BB*KVL*NH) return;
    int b = w / (KVL*NH), rem = w % (KVL*NH);
    int p = rem / NH, h = rem % NH;
    size_t ko = ((((size_t)b*KVL + p)*2 + 0)*NH + h)*HD;
    float k0 = kvout[ko + lane], k1 = kvout[ko + lane + 32];
    size_t vo = ko + (size_t)NH*HD;
    float v0 = kvout[vo + lane], v1 = kvout[vo + lane + 32];
    int ti = p*32 + lane;
    float s = rs_[ti], c = rc_[ti];
    float r0 = k0*c - k1*s;
    float r1 = k1*c + k0*s;
    size_t o = (((size_t)b*NH + h)*KVL + p)*HD;
    __nv_bfloat16 h0,l0,h1,l1;
    split2(r0,h0,l0); split2(r1,h1,l1);
    ksh[o + lane] = h0;      ksl[o + lane] = l0;
    ksh[o + lane + 32] = h1; ksl[o + lane + 32] = l1;
    split2(v0,h0,l0); split2(v1,h1,l1);
    vsh[o + lane] = h0;      vsl[o + lane] = l0;
    vsh[o + lane + 32] = h1; vsl[o + lane + 32] = l1;
}

// ================= flash attention with mma.sync (bf16 hi/lo) =================
#define FA_STRB 144
#define FA_TB   (64*FA_STRB)            // 9216 B per tile
#define FA_SQ   (2*FA_TB)               // Q region
#define FA_STG  (4*FA_TB)               // per stage (Kh,Kl,Vh,Vl)
#define FA_SMEM (FA_SQ + 2*FA_STG)      // 92160 B
#define FA_NT   (KVL/64)                // 40 kv tiles

__global__ void __launch_bounds__(128)
fa_mma_k(const __nv_bfloat16* __restrict__ Qh, const __nv_bfloat16* __restrict__ Ql,
         const __nv_bfloat16* __restrict__ Kh, const __nv_bfloat16* __restrict__ Kl,
         const __nv_bfloat16* __restrict__ Vh, const __nv_bfloat16* __restrict__ Vl,
         __nv_bfloat16* __restrict__ Oh, __nv_bfloat16* __restrict__ Ol){
    extern __shared__ char smc[];
    uint32_t sb = _s2u(smc);
    int qt = blockIdx.x, h = blockIdx.y, b = blockIdx.z;
    int tid = threadIdx.x, wid = tid>>5, lane = tid&31;

    size_t bh = (size_t)b*NH + h;
    const __nv_bfloat16* gqh = Qh + (bh*NN + qt*64)*HD;
    const __nv_bfloat16* gql = Ql + (bh*NN + qt*64)*HD;
    const __nv_bfloat16* gkh = Kh + bh*KVL*HD;
    const __nv_bfloat16* gkl = Kl + bh*KVL*HD;
    const __nv_bfloat16* gvh = Vh + bh*KVL*HD;
    const __nv_bfloat16* gvl = Vl + bh*KVL*HD;

    #pragma unroll
    for (int i = 0; i < 8; i++){
        int idx = tid + i*128;
        int t = idx >> 9, pos = idx & 511;
        int row = pos >> 3, seg = pos & 7;
        const __nv_bfloat16* g = (t ? gql : gqh) + (size_t)row*HD + seg*8;
        CP16(sb + t*FA_TB + row*FA_STRB + seg*16, g);
    }
    CPCOMMIT();
    {
        uint32_t st = sb + FA_SQ;
        #pragma unroll
        for (int i = 0; i < 16; i++){
            int idx = tid + i*128;
            int t = idx >> 9, pos = idx & 511;
            int row = pos >> 3, seg = pos & 7;
            const __nv_bfloat16* g = (t==0? gkh : t==1? gkl : t==2? gvh : gvl)
                                   + (size_t)row*HD + seg*8;
            CP16(st + t*FA_TB + row*FA_STRB + seg*16, g);
        }
        CPCOMMIT();
    }

    CPWAITG(1);
    __syncthreads();
    uint32_t qfh[4][4], qfl[4][4];
    {
        int arow = wid*16 + (lane & 15);
        int kc = (lane >> 4) * 8;
        #pragma unroll
        for (int kk = 0; kk < 4; kk++){
            uint32_t addr = sb + arow*FA_STRB + (kk*16 + kc)*2;
            ldsm_x4(addr, qfh[kk]);
            ldsm_x4(addr + FA_TB, qfl[kk]);
        }
    }

    float acc[8][4];
    #pragma unroll
    for (int j = 0; j < 8; j++){
        #pragma unroll
        for (int q = 0; q < 4; q++) acc[j][q] = 0.f;
    }
    float m0 = -1e30f, m1 = -1e30f, l0 = 0.f, l1 = 0.f;

    for (int it = 0; it < FA_NT; it++){
        if (it + 1 < FA_NT){
            uint32_t st = sb + FA_SQ + ((it+1)&1)*FA_STG;
            int p0 = (it+1)*64;
            #pragma unroll
            for (int i = 0; i < 16; i++){
                int idx = tid + i*128;
                int t = idx >> 9, pos = idx & 511;
                int row = pos >> 3, seg = pos & 7;
                const __nv_bfloat16* g = (t==0? gkh : t==1? gkl : t==2? gvh : gvl)
                                       + (size_t)(p0+row)*HD + seg*8;
                CP16(st + t*FA_TB + row*FA_STRB + seg*16, g);
            }
            CPCOMMIT();
        }
        if (it + 1 < FA_NT) { CPWAITG(1); } else { CPWAITG(0); }
        __syncthreads();

        uint32_t st = sb + FA_SQ + (it&1)*FA_STG;
        uint32_t smKh = st, smVh = st + 2*FA_TB;

        float s[8][4];
        int l16 = lane & 15;
        int brow = lane & 7;
        int bkc = ((lane >> 3) & 1) * 8;
        #pragma unroll
        for (int j = 0; j < 8; j++){
            #pragma unroll
            for (int q = 0; q < 4; q++) s[j][q] = 0.f;
            #pragma unroll
            for (int kk = 0; kk < 4; kk++){
                uint32_t addr = smKh + (j*8 + brow)*FA_STRB + (kk*16 + bkc)*2;
                uint32_t kbh[2], kbl[2];
                ldsm_x2(addr, kbh);
                ldsm_x2(addr + FA_TB, kbl);
                mma16816(s[j], qfh[kk], kbh);
                mma16816(s[j], qfh[kk], kbl);
                mma16816(s[j], qfl[kk], kbh);
            }
        }

        float mx0 = -1e30f, mx1 = -1e30f;
        #pragma unroll
        for (int j = 0; j < 8; j++){
            mx0 = fmaxf(mx0, fmaxf(s[j][0], s[j][1]));
            mx1 = fmaxf(mx1, fmaxf(s[j][2], s[j][3]));
        }
        #pragma unroll
        for (int off = 1; off < 4; off <<= 1){
            mx0 = fmaxf(mx0, __shfl_xor_sync(0xffffffffu, mx0, off));
            mx1 = fmaxf(mx1, __shfl_xor_sync(0xffffffffu, mx1, off));
        }
        float mn0 = fmaxf(m0, mx0), mn1 = fmaxf(m1, mx1);
        float c0 = __expf(m0 - mn0), c1 = __expf(m1 - mn1);
        m0 = mn0; m1 = mn1;
        l0 *= c0; l1 *= c1;
        #pragma unroll
        for (int j = 0; j < 8; j++){
            acc[j][0] *= c0; acc[j][1] *= c0;
            acc[j][2] *= c1; acc[j][3] *= c1;
        }
        uint32_t phi[8][2], plo[8][2];
        #pragma unroll
        for (int j = 0; j < 8; j++){
            float p0 = __expf(s[j][0] - mn0);
            float p1 = __expf(s[j][1] - mn0);
            float p2 = __expf(s[j][2] - mn1);
            float p3 = __expf(s[j][3] - mn1);
            l0 += p0 + p1; l1 += p2 + p3;
            pack_hl(p0, p1, phi[j][0], plo[j][0]);
            pack_hl(p2, p3, phi[j][1], plo[j][1]);
        }

        #pragma unroll
        for (int kk = 0; kk < 4; kk++){
            uint32_t pah[4] = { phi[2*kk][0], phi[2*kk][1], phi[2*kk+1][0], phi[2*kk+1][1] };
            uint32_t pal[4] = { plo[2*kk][0], plo[2*kk][1], plo[2*kk+1][0], plo[2*kk+1][1] };
            #pragma unroll
            for (int j = 0; j < 8; j++){
                uint32_t addr = smVh + (kk*16 + l16)*FA_STRB + j*8*2;
                uint32_t vbh[2], vbl[2];
                ldsm_x2t(addr, vbh);
                ldsm_x2t(addr + FA_TB, vbl);
                mma16816(acc[j], pah, vbh);
                mma16816(acc[j], pah, vbl);
                mma16816(acc[j], pal, vbh);
            }
        }
        __syncthreads();
    }

    #pragma unroll
    for (int off = 1; off < 4; off <<= 1){
        l0 += __shfl_xor_sync(0xffffffffu, l0, off);
        l1 += __shfl_xor_sync(0xffffffffu, l1, off);
    }
    float rl0 = 1.f / l0, rl1 = 1.f / l1;

    int q0r = qt*64 + wid*16 + (lane >> 2);
    int cc = (lane & 3)*2;
    #pragma unroll
    for (int j = 0; j < 8; j++){
        int col = h*HD + j*8 + cc;
        float o0 = acc[j][0]*rl0, o1 = acc[j][1]*rl0;
        uint32_t hw, lw; pack_hl(o0, o1, hw, lw);
        size_t off0 = (size_t)(b*NN + q0r)*DM + col;
        *reinterpret_cast<uint32_t*>(&Oh[off0]) = hw;
        *reinterpret_cast<uint32_t*>(&Ol[off0]) = lw;
        float o2 = acc[j][2]*rl1, o3 = acc[j][3]*rl1;
        pack_hl(o2, o3, hw, lw);
        size_t off1 = (size_t)(b*NN + q0r + 8)*DM + col;
        *reinterpret_cast<uint32_t*>(&Oh[off1]) = hw;
        *reinterpret_cast<uint32_t*>(&Ol[off1]) = lw;
    }
}

// ---------------- GLU ----------------
__global__ void glu_k(const float* __restrict__ in, float* __restrict__ out) {
    int idx = blockIdx.x*blockDim.x + threadIdx.x;
    if (idx >= RR*DM) return;
    int r = idx / DM, c = idx % DM;
    float a = in[(size_t)r*(2*DM) + c];
    float g = in[(size_t)r*(2*DM) + DM + c];
    out[idx] = a / (1.f + expf(-g));
}

// ---------------- depthwise conv: 8 outputs/thread, register sliding window ----------------
__global__ void __launch_bounds__(256)
dwconv8_k(const float* __restrict__ in, const float* __restrict__ w,
          const float* __restrict__ bias, float* __restrict__ out) {
    int n8 = blockIdx.x;
    int b  = blockIdx.y;
    int n0 = n8*8;
    const float* bin = in + (size_t)b*NN*DM;
    float* bout = out + (size_t)b*NN*DM;
    #pragma unroll
    for (int cc = 0; cc < 3; cc++){
        int c = threadIdx.x + cc*256;
        const float* wr = w + c*KSZ;
        float win[38];
        #pragma unroll
        for (int j = 0; j < 38; j++){
            int nn = n0 + j - (KSZ/2);
            win[j] = (nn >= 0 && nn < NN) ? bin[(size_t)nn*DM + c] : 0.f;
        }
        float bv = bias[c];
        float acc[8];
        #pragma unroll
        for (int i = 0; i < 8; i++) acc[i] = bv;
        #pragma unroll
        for (int t = 0; t < KSZ; t++){
            float wv = wr[t];
            #pragma unroll
            for (int i = 0; i < 8; i++) acc[i] += win[i+t]*wv;
        }
        #pragma unroll
        for (int i = 0; i < 8; i++) bout[(size_t)(n0+i)*DM + c] = acc[i];
    }
}

// ---------------- batchnorm stats pass1: coalesced partial sums ----------------
__global__ void __launch_bounds__(256)
bnstats1_k(const float* __restrict__ x, float* __restrict__ p1, float* __restrict__ p2) {
    int blk = blockIdx.x;
    int r0 = blk * (RR/BN_BLKS);
    #pragma unroll
    for (int cc = 0; cc < 3; cc++){
        int c = threadIdx.x + cc*256;
        float s = 0.f, s2 = 0.f;
        #pragma unroll 4
        for (int r = 0; r < RR/BN_BLKS; r++){
            float v = x[(size_t)(r0+r)*DM + c];
            s += v; s2 += v*v;
        }
        p1[(size_t)blk*DM + c] = s;
        p2[(size_t)blk*DM + c] = s2;
    }
}

// ---------------- batchnorm stats pass2 ----------------
__global__ void bnstats2_k(const float* __restrict__ p1, const float* __restrict__ p2,
                           float* __restrict__ mean, float* __restrict__ var) {
    int c = blockIdx.x*blockDim.x + threadIdx.x;
    if (c >= DM) return;
    float s = 0.f, s2 = 0.f;
    for (int b = 0; b < BN_BLKS; b++){
        s  += p1[(size_t)b*DM + c];
        s2 += p2[(size_t)b*DM + c];
    }
    float m = s * (1.f/RR);
    mean[c] = m;
    var[c] = s2 * (1.f/RR) - m*m;
}

// ---------------- batchnorm apply + swish -> bf16 hi/lo ----------------
__global__ void bnapply_split_k(const float* __restrict__ x, const float* __restrict__ mean,
                                const float* __restrict__ var, const float* __restrict__ g,
                                const float* __restrict__ b,
                                __nv_bfloat16* __restrict__ hi, __nv_bfloat16* __restrict__ lo) {
    int idx = blockIdx.x*blockDim.x + threadIdx.x;
    if (idx >= RR*DM) return;
    int c = idx % DM;
    float v = (x[idx] - mean[c]) * rsqrtf(var[c] + EPS) * g[c] + b[c];
    v = v / (1.f + expf(-v));
    __nv_bfloat16 h, l; split2(v, h, l);
    hi[idx] = h; lo[idx] = l;
}

// ---------------- launch ----------------
extern "C" void kernel_launch(void* const* d_in, const int* in_sizes, int n_in,
                              void* d_out, int out_size) {
    const float* x_in      = (const float*)d_in[0];
    const float* cached    = (const float*)d_in[4];
    const float* ff1_nw    = (const float*)d_in[5];
    const float* ff1_w1    = (const float*)d_in[6];
    const float* ff1_b1    = (const float*)d_in[7];
    const float* ff1_w2    = (const float*)d_in[8];
    const float* ff1_b2    = (const float*)d_in[9];
    const float* attn_nw   = (const float*)d_in[10];
    const float* qkv_w     = (const float*)d_in[11];
    const float* out_w     = (const float*)d_in[12];
    const float* q_nw      = (const float*)d_in[13];
    const float* k_nw      = (const float*)d_in[14];
    const float* conv_nw   = (const float*)d_in[15];
    const float* pw1_w     = (const float*)d_in[16];
    const float* pw1_b     = (const float*)d_in[17];
    const float* dw_w      = (const float*)d_in[18];
    const float* dw_b      = (const float*)d_in[19];
    const float* bn_g      = (const float*)d_in[20];
    const float* bn_b      = (const float*)d_in[21];
    const float* pw2_w     = (const float*)d_in[22];
    const float* pw2_b     = (const float*)d_in[23];
    const float* ff2_nw    = (const float*)d_in[24];
    const float* ff2_w1    = (const float*)d_in[25];
    const float* ff2_b1    = (const float*)d_in[26];
    const float* ff2_w2    = (const float*)d_in[27];
    const float* ff2_b2    = (const float*)d_in[28];
    const float* out_nw    = (const float*)d_in[29];

    float* outx  = (float*)d_out;
    float* kvout = outx + (size_t)RR*DM;

    float *x_, *ff_, *qkv_, *glu_, *dw_, *mean_, *var_, *rs_, *rc_, *bnp1_, *bnp2_;
    __nv_bfloat16 *wth_, *wtl_, *abh_, *abl_, *a1h_, *a1l_, *qsh_, *qsl_, *ksh_, *ksl_, *vsh_, *vsl_;
    cudaGetSymbolAddress((void**)&x_,    g_x);
    cudaGetSymbolAddress((void**)&ff_,   g_ff);
    cudaGetSymbolAddress((void**)&qkv_,  g_qkv);
    cudaGetSymbolAddress((void**)&glu_,  g_glu);
    cudaGetSymbolAddress((void**)&dw_,   g_dw);
    cudaGetSymbolAddress((void**)&mean_, g_mean);
    cudaGetSymbolAddress((void**)&var_,  g_var);
    cudaGetSymbolAddress((void**)&rs_,   g_rs);
    cudaGetSymbolAddress((void**)&rc_,   g_rc);
    cudaGetSymbolAddress((void**)&bnp1_, g_bnp1);
    cudaGetSymbolAddress((void**)&bnp2_, g_bnp2);
    cudaGetSymbolAddress((void**)&wth_,  g_wth);
    cudaGetSymbolAddress((void**)&wtl_,  g_wtl);
    cudaGetSymbolAddress((void**)&abh_,  g_abh);
    cudaGetSymbolAddress((void**)&abl_,  g_abl);
    cudaGetSymbolAddress((void**)&a1h_,  g_a1h);
    cudaGetSymbolAddress((void**)&a1l_,  g_a1l);
    cudaGetSymbolAddress((void**)&qsh_,  g_qsh);
    cudaGetSymbolAddress((void**)&qsl_,  g_qsl);
    cudaGetSymbolAddress((void**)&ksh_,  g_ksh);
    cudaGetSymbolAddress((void**)&ksl_,  g_ksl);
    cudaGetSymbolAddress((void**)&vsh_,  g_vsh);
    cudaGetSymbolAddress((void**)&vsl_,  g_vsl);

    static int attr_set = 0;
    if (!attr_set) {
        cudaFuncSetAttribute(fa_mma_k, cudaFuncAttributeMaxDynamicSharedMemorySize, FA_SMEM);
        cudaFuncSetAttribute(tgemm_k<0,0>, cudaFuncAttributeMaxDynamicSharedMemorySize, GSM);
        cudaFuncSetAttribute(tgemm_k<1,1>, cudaFuncAttributeMaxDynamicSharedMemorySize, GSM);
        cudaFuncSetAttribute(tgemm_sk_k, cudaFuncAttributeMaxDynamicSharedMemorySize, GSM);
        attr_set = 1;
    }

    // weight offsets (transposed [N,K] layouts) — must match wsplit_all_k's segDst
    size_t o = 0;
    size_t off_qkv = o; o += (size_t)(3*NH*HD)*DM;
    size_t off_out = o; o += (size_t)DM*DM;
    size_t off_f1a = o; o += (size_t)FF*DM;
    size_t off_f1b = o; o += (size_t)DM*FF;
    size_t off_pw1 = o; o += (size_t)(2*DM)*DM;
    size_t off_pw2 = o; o += (size_t)DM*DM;
    size_t off_f2a = o; o += (size_t)FF*DM;
    size_t off_f2b = o; o += (size_t)DM*FF;

    wsplit_all_k<<<13248, 256>>>(qkv_w, out_w, ff1_w1, ff1_w2, pw1_w, pw2_w, ff2_w1, ff2_w2,
                                 wth_, wtl_);
    rope_table_k<<<(KVL*32 + 255)/256, 256>>>(rs_, rc_);

    cudaMemcpyAsync(x_, x_in, sizeof(float)*(size_t)RR*DM, cudaMemcpyDeviceToDevice, 0);

    const int EW = (RR*DM + 255)/256;

    // ---- FF1  (second GEMM via split-K into g_ff partials, then combine)
    rmsnorm_split_k<<<RR, 256>>>(x_, ff1_nw, a1h_, a1l_);
    tgemm_k<1,1><<<dim3(FF/128, RR/128), 256, GSM>>>(a1h_, a1l_, wth_+off_f1a, wtl_+off_f1a,
                                                     ff1_b1, nullptr, nullptr, abh_, abl_, FF, DM);
    tgemm_sk_k<<<dim3(DM/128, RR/128, 2), 256, GSM>>>(abh_, abl_, wth_+off_f1b, wtl_+off_f1b,
                                                      ff_, DM, FF);
    comb_half_k<<<EW, 256>>>(ff_, ff1_b2, x_, x_);

    // ---- Attention
    rmsnorm_split_k<<<RR, 256>>>(x_, attn_nw, a1h_, a1l_);
    tgemm_k<0,0><<<dim3((3*NH*HD)/128, RR/128), 256, GSM>>>(a1h_, a1l_, wth_+off_qkv, wtl_+off_qkv,
                                                            nullptr, nullptr, qkv_, nullptr, nullptr,
                                                            3*NH*HD, DM);
    copy_cache_k<<<(BB*CCH*2*NH*HD + 255)/256, 256>>>(cached, kvout);
    qkv_post_k<<<RR*NH/4, 128>>>(qkv_, q_nw, k_nw, kvout, qsh_, qsl_, rs_, rc_);
    kvsplit_k<<<BB*KVL*NH/4, 128>>>(kvout, ksh_, ksl_, vsh_, vsl_, rs_, rc_);
    fa_mma_k<<<dim3(NN/64, NH, BB), 128, FA_SMEM>>>(qsh_, qsl_, ksh_, ksl_, vsh_, vsl_, a1h_, a1l_);
    tgemm_k<0,0><<<dim3(DM/128, RR/128), 256, GSM>>>(a1h_, a1l_, wth_+off_out, wtl_+off_out,
                                                     nullptr, x_, x_, nullptr, nullptr, DM, DM);

    // ---- Conv module
    rmsnorm_split_k<<<RR, 256>>>(x_, conv_nw, a1h_, a1l_);
    tgemm_k<0,0><<<dim3((2*DM)/128, RR/128), 256, GSM>>>(a1h_, a1l_, wth_+off_pw1, wtl_+off_pw1,
                                                         pw1_b, nullptr, ff_, nullptr, nullptr,
                                                         2*DM, DM);
    glu_k<<<EW, 256>>>(ff_, glu_);
    dwconv8_k<<<dim3(NN/8, BB), 256>>>(glu_, dw_w, dw_b, dw_);
    bnstats1_k<<<BN_BLKS, 256>>>(dw_, bnp1_, bnp2_);
    bnstats2_k<<<(DM + 255)/256, 256>>>(bnp1_, bnp2_, mean_, var_);
    bnapply_split_k<<<EW, 256>>>(dw_, mean_, var_, bn_g, bn_b, a1h_, a1l_);
    tgemm_k<0,0><<<dim3(DM/128, RR/128), 256, GSM>>>(a1h_, a1l_, wth_+off_pw2, wtl_+off_pw2,
                                                     pw2_b, nullptr, x_, nullptr, nullptr, DM, DM);

    // ---- FF2  (second GEMM via split-K)
    rmsnorm_split_k<<<RR, 256>>>(x_, ff2_nw, a1h_, a1l_);
    tgemm_k<1,1><<<dim3(FF/128, RR/128), 256, GSM>>>(a1h_, a1l_, wth_+off_f2a, wtl_+off_f2a,
                                                     ff2_b1, nullptr, nullptr, abh_, abl_, FF, DM);
    tgemm_sk_k<<<dim3(DM/128, RR/128, 2), 256, GSM>>>(abh_, abl_, wth_+off_f2b, wtl_+off_f2b,
                                                      ff_, DM, FF);
    comb_half_k<<<EW, 256>>>(ff_, ff2_b2, x_, x_);

    // ---- final rmsnorm -> output x
    rmsnorm_k<<<RR, 256>>>(x_, out_nw, outx);
}